// round 1
// baseline (speedup 1.0000x reference)
#include <cuda_runtime.h>
#include <math.h>
#include <stdint.h>

#define NN 50000
#define EE 512000
#define E2 (EE/2)
#define DINF 128
#define HC 128
#define CC 32
#define HH 4

// ---------------- scratch (device globals; no allocations allowed) ----------------
__device__ float    g_q[NN*HC];
__device__ float    g_k[NN*HC];
__device__ float    g_v[NN*HC];
__device__ float    g_ea2[(size_t)EE*HC];
__device__ float    g_ea3[(size_t)EE*HC];
__device__ float    g_l1[EE*HH];     // logits1 -> overwritten with exp
__device__ float    g_l2[EE*HH];
__device__ unsigned g_m1[NN*HH];     // order-encoded float max
__device__ unsigned g_m2[NN*HH];
__device__ float    g_s1[NN*HH];
__device__ float    g_s2[NN*HH];
__device__ float    g_xgat[NN*CC];
__device__ double   g_sum[CC];
__device__ double   g_sumsq[CC];
__device__ float    g_mu[CC];
__device__ float    g_rstd[CC];
__device__ int      g_degb[NN];
__device__ float    g_acc[NN*CC];
__device__ float    g_o1[NN*CC];
__device__ float    g_attr[NN*CC];
__device__ float    g_xh[(size_t)E2*CC];

// ---------------- helpers ----------------
__device__ __forceinline__ unsigned fenc(float f) {
    unsigned u = __float_as_uint(f);
    return (u & 0x80000000u) ? ~u : (u | 0x80000000u);
}
__device__ __forceinline__ float fdec(unsigned u) {
    return (u & 0x80000000u) ? __uint_as_float(u & 0x7FFFFFFFu) : __uint_as_float(~u);
}

// ---------------- zero scratch ----------------
__global__ void zero_kernel() {
    int i = blockIdx.x * blockDim.x + threadIdx.x;
    int stride = gridDim.x * blockDim.x;
    for (int j = i; j < NN*HH; j += stride) { g_m1[j]=0u; g_m2[j]=0u; g_s1[j]=0.f; g_s2[j]=0.f; }
    for (int j = i; j < NN*CC; j += stride) { g_xgat[j]=0.f; g_acc[j]=0.f; }
    for (int j = i; j < NN;    j += stride) { g_degb[j]=0; }
    if (i < CC) { g_sum[i]=0.0; g_sumsq[i]=0.0; }
}

// ---------------- register-tiled SGEMM: C[M,N] = A[M,K] @ W[K,N] + bias ----------------
template<int BM, int BN, int BK, int TM, int TN>
__global__ void gemm_bias(const float* __restrict__ A, const float* __restrict__ W,
                          const float* __restrict__ bias, float* __restrict__ C,
                          int M, int N, int K) {
    constexpr int THREADS = (BM/TM)*(BN/TN);
    __shared__ float As[BK][BM + 4];
    __shared__ float Ws[BK][BN];
    int tid  = threadIdx.x;
    int brow = blockIdx.y * BM;
    int bcol = blockIdx.x * BN;
    int trow = (tid / (BN/TN)) * TM;
    int tcol = (tid % (BN/TN)) * TN;
    float acc[TM][TN];
    #pragma unroll
    for (int i = 0; i < TM; i++)
        #pragma unroll
        for (int j = 0; j < TN; j++) acc[i][j] = 0.f;

    for (int k0 = 0; k0 < K; k0 += BK) {
        #pragma unroll
        for (int i = tid; i < BM*BK; i += THREADS) {
            int m = i / BK, kk = i % BK;
            int gm = brow + m;
            As[kk][m] = (gm < M) ? A[(size_t)gm*K + k0 + kk] : 0.f;
        }
        #pragma unroll
        for (int i = tid; i < BK*BN; i += THREADS) {
            int kk = i / BN, nn = i % BN;
            Ws[kk][nn] = W[(size_t)(k0+kk)*N + bcol + nn];
        }
        __syncthreads();
        #pragma unroll
        for (int kk = 0; kk < BK; kk++) {
            float ra[TM], rb[TN];
            #pragma unroll
            for (int i = 0; i < TM; i++) ra[i] = As[kk][trow + i];
            #pragma unroll
            for (int j = 0; j < TN; j++) rb[j] = Ws[kk][tcol + j];
            #pragma unroll
            for (int i = 0; i < TM; i++)
                #pragma unroll
                for (int j = 0; j < TN; j++)
                    acc[i][j] = fmaf(ra[i], rb[j], acc[i][j]);
        }
        __syncthreads();
    }
    #pragma unroll
    for (int i = 0; i < TM; i++) {
        int gm = brow + trow + i;
        if (gm >= M) continue;
        #pragma unroll
        for (int j = 0; j < TN; j++) {
            int gn = bcol + tcol + j;
            float bv = bias ? bias[gn] : 0.f;
            C[(size_t)gm*N + gn] = acc[i][j] + bv;
        }
    }
}

// ---------------- attention pass 1: logits + segment max (warp per edge) ----------------
__global__ void attn_logits(const int* __restrict__ ei) {
    int e = (blockIdx.x * blockDim.x + threadIdx.x) >> 5;
    if (e >= EE) return;
    int lane = threadIdx.x & 31;
    int s = ei[e], d = ei[EE + e];
    const float scale = 0.17677669529663687f;  // 1/sqrt(32)
    #pragma unroll
    for (int h = 0; h < HH; h++) {
        float qv  = g_q[d*HC + h*32 + lane];
        float kv  = g_k[s*HC + h*32 + lane];
        float e2v = g_ea2[(size_t)e*HC + h*32 + lane];
        float p1 = qv * kv;
        float p2 = qv * e2v;
        #pragma unroll
        for (int o = 16; o > 0; o >>= 1) {
            p1 += __shfl_xor_sync(0xffffffffu, p1, o);
            p2 += __shfl_xor_sync(0xffffffffu, p2, o);
        }
        if (lane == h) {
            float l1 = p1 * scale, l2 = p2 * scale;
            g_l1[e*HH + h] = l1;
            g_l2[e*HH + h] = l2;
            atomicMax(&g_m1[d*HH + h], fenc(l1));
            atomicMax(&g_m2[d*HH + h], fenc(l2));
        }
    }
}

// ---------------- attention pass 2: exp + segment sum ----------------
__global__ void attn_exp(const int* __restrict__ ei) {
    int idx = blockIdx.x * blockDim.x + threadIdx.x;
    if (idx >= EE*HH) return;
    int e = idx >> 2, h = idx & 3;
    int d = ei[EE + e];
    float m1 = fdec(g_m1[d*HH + h]);
    float m2 = fdec(g_m2[d*HH + h]);
    float ex1 = __expf(g_l1[idx] - m1);
    float ex2 = __expf(g_l2[idx] - m2);
    g_l1[idx] = ex1;
    g_l2[idx] = ex2;
    atomicAdd(&g_s1[d*HH + h], ex1);
    atomicAdd(&g_s2[d*HH + h], ex2);
}

// ---------------- attention pass 3: msg @ Wcon + scatter (warp per edge) ----------------
__global__ void attn_msg(const int* __restrict__ ei, const float* __restrict__ Wcon) {
    __shared__ float sW[HC][CC];
    __shared__ float smsg[8][HC];
    int tid = threadIdx.x;
    for (int i = tid; i < HC*CC; i += 256) sW[i / CC][i % CC] = Wcon[i];
    __syncthreads();
    int w = tid >> 5, lane = tid & 31;
    int e = blockIdx.x * 8 + w;
    if (e < EE) {
        int s = ei[e], d = ei[EE + e];
        #pragma unroll
        for (int h = 0; h < HH; h++) {
            float a1 = g_l1[e*HH + h] / (g_s1[d*HH + h] + 1e-16f);
            float a2 = g_l2[e*HH + h] / (g_s2[d*HH + h] + 1e-16f);
            float msgk = g_v[s*HC + h*32 + lane] * a1
                       + g_ea3[(size_t)e*HC + h*32 + lane] * a2;
            smsg[w][h*32 + lane] = msgk;
        }
        __syncwarp();
        float out = 0.f;
        #pragma unroll
        for (int kk = 0; kk < HC; kk++)
            out = fmaf(smsg[w][kk], sW[kk][lane], out);
        atomicAdd(&g_xgat[d*CC + lane], out);
    }
}

// ---------------- BatchNorm stats / finalize / apply+GELU ----------------
__global__ void bn_stats() {
    __shared__ float ssum[8][CC], ssq[8][CC];
    int c  = threadIdx.x & 31;
    int ry = threadIdx.x >> 5;
    float s = 0.f, q = 0.f;
    for (int r = blockIdx.x * 8 + ry; r < NN; r += gridDim.x * 8) {
        float v = g_xgat[r*CC + c];
        s += v; q += v * v;
    }
    ssum[ry][c] = s; ssq[ry][c] = q;
    __syncthreads();
    if (ry == 0) {
        #pragma unroll
        for (int i = 1; i < 8; i++) { s += ssum[i][c]; q += ssq[i][c]; }
        atomicAdd(&g_sum[c],   (double)s);
        atomicAdd(&g_sumsq[c], (double)q);
    }
}

__global__ void bn_final() {
    int c = threadIdx.x;
    if (c < CC) {
        double mu  = g_sum[c] / (double)NN;
        double var = g_sumsq[c] / (double)NN - mu * mu;
        g_mu[c]   = (float)mu;
        g_rstd[c] = (float)(1.0 / sqrt(var + 1e-5));
    }
}

__global__ void bn_apply(const float* __restrict__ bn_w, const float* __restrict__ bn_b,
                         float* __restrict__ out1) {
    int i = blockIdx.x * blockDim.x + threadIdx.x;
    if (i >= NN*CC) return;
    int c = i & 31;
    float xn = bn_w[c] * (g_xgat[i] - g_mu[c]) * g_rstd[c] + bn_b[c];
    out1[i] = 0.5f * xn * (1.0f + erff(xn * 0.70710678118654752f));
}

// ---------------- hypergraph branch ----------------
__global__ void hyper_deg(const int* __restrict__ ei) {
    int i = blockIdx.x * blockDim.x + threadIdx.x;
    if (i >= E2) return;
    atomicAdd(&g_degb[ei[i]],      1);
    atomicAdd(&g_degb[ei[EE + i]], 1);
}

__global__ void hyper_acc(const int* __restrict__ ei) {
    int idx = blockIdx.x * blockDim.x + threadIdx.x;
    if (idx >= E2*CC) return;
    int i = idx >> 5, c = idx & 31;
    float xv = g_xh[idx];
    atomicAdd(&g_acc[ei[i]*CC + c],      xv);
    atomicAdd(&g_acc[ei[EE + i]*CC + c], xv);
}

__global__ void hyper_o1() {
    int idx = blockIdx.x * blockDim.x + threadIdx.x;
    if (idx >= NN*CC) return;
    int n = idx >> 5;
    int deg = g_degb[n];
    float binv = (deg > 0) ? (1.0f / (float)deg) : 0.f;
    g_o1[idx] = g_acc[idx] * binv + g_attr[idx];
}

__global__ void hyper_out(const int* __restrict__ ei, const float* __restrict__ bh,
                          float* __restrict__ out2) {
    int idx = blockIdx.x * blockDim.x + threadIdx.x;
    if (idx >= E2*CC) return;
    int i = idx >> 5, c = idx & 31;
    out2[idx] = 0.5f * (g_o1[ei[i]*CC + c] + g_o1[ei[EE + i]*CC + c]) + bh[c];
}

// ---------------- launcher ----------------
extern "C" void kernel_launch(void* const* d_in, const int* in_sizes, int n_in,
                              void* d_out, int out_size) {
    const float* x    = (const float*)d_in[0];
    const float* ea   = (const float*)d_in[1];
    const float* Wq   = (const float*)d_in[2];
    const float* bq   = (const float*)d_in[3];
    const float* Wk   = (const float*)d_in[4];
    const float* bk   = (const float*)d_in[5];
    const float* Wv   = (const float*)d_in[6];
    const float* bv   = (const float*)d_in[7];
    const float* We2  = (const float*)d_in[8];
    const float* be2  = (const float*)d_in[9];
    const float* We3  = (const float*)d_in[10];
    const float* be3  = (const float*)d_in[11];
    const float* Wcon = (const float*)d_in[12];
    const float* bn_w = (const float*)d_in[13];
    const float* bn_b = (const float*)d_in[14];
    const float* Wh1  = (const float*)d_in[15];
    const float* Wh2  = (const float*)d_in[16];
    const float* bh   = (const float*)d_in[17];
    const int*   ei   = (const int*)d_in[18];
    // d_in[19] = batch, unused (BN is global)

    float* out  = (float*)d_out;
    float* out1 = out;                       // x_gat: NN*CC
    float* out2 = out + (size_t)NN * CC;     // edge_attr2: E2*CC

    float *pq, *pk, *pv, *pea2, *pea3, *pattr, *pxh;
    cudaGetSymbolAddress((void**)&pq,    g_q);
    cudaGetSymbolAddress((void**)&pk,    g_k);
    cudaGetSymbolAddress((void**)&pv,    g_v);
    cudaGetSymbolAddress((void**)&pea2,  g_ea2);
    cudaGetSymbolAddress((void**)&pea3,  g_ea3);
    cudaGetSymbolAddress((void**)&pattr, g_attr);
    cudaGetSymbolAddress((void**)&pxh,   g_xh);

    zero_kernel<<<512, 256>>>();

    // node projections: [50000,128] @ [128,128]
    dim3 gN(1, (NN + 127) / 128);
    gemm_bias<128,128,16,8,8><<<gN, 256>>>(x, Wq, bq, pq, NN, HC, DINF);
    gemm_bias<128,128,16,8,8><<<gN, 256>>>(x, Wk, bk, pk, NN, HC, DINF);
    gemm_bias<128,128,16,8,8><<<gN, 256>>>(x, Wv, bv, pv, NN, HC, DINF);

    // edge projections: [512000,128] @ [128,128]
    dim3 gE(1, EE / 128);
    gemm_bias<128,128,16,8,8><<<gE, 256>>>(ea, We2, be2, pea2, EE, HC, DINF);
    gemm_bias<128,128,16,8,8><<<gE, 256>>>(ea, We3, be3, pea3, EE, HC, DINF);

    // attention: logits + max, exp + sum, msg + scatter
    attn_logits<<<EE / 8, 256>>>(ei);
    attn_exp<<<(EE * HH + 255) / 256, 256>>>(ei);
    attn_msg<<<EE / 8, 256>>>(ei, Wcon);

    // batchnorm + gelu -> out1
    bn_stats<<<256, 256>>>();
    bn_final<<<1, 32>>>();
    bn_apply<<<(NN * CC + 255) / 256, 256>>>(bn_w, bn_b, out1);

    // hypergraph branch
    gemm_bias<128,32,16,8,4><<<dim3(1, (NN + 127) / 128), 128>>>(x,  Wh2, nullptr, pattr, NN, CC, DINF);
    gemm_bias<128,32,16,8,4><<<dim3(1, E2 / 128),         128>>>(ea, Wh1, nullptr, pxh,  E2, CC, DINF);
    hyper_deg<<<(E2 + 255) / 256, 256>>>(ei);
    hyper_acc<<<(E2 * CC + 255) / 256, 256>>>(ei);
    hyper_o1<<<(NN * CC + 255) / 256, 256>>>();
    hyper_out<<<(E2 * CC + 255) / 256, 256>>>(ei, bh, out2);
}

// round 2
// speedup vs baseline: 1.8503x; 1.8503x over previous
#include <cuda_runtime.h>
#include <math.h>
#include <stdint.h>

#define NN 50000
#define EE 512000
#define E2 (EE/2)
#define DINF 128
#define HC 128
#define CC 32
#define HH 4

// ---------------- scratch (device globals; no allocations allowed) ----------------
__device__ float    g_q[NN*HC];
__device__ float    g_k[NN*HC];
__device__ float    g_v[NN*HC];
__device__ float    g_u[(size_t)NN*HH*DINF];   // u[n][h][f]
__device__ float    g_we2t[DINF*HC];           // We2 transposed: [out][f]
__device__ float    g_ea3[(size_t)EE*HC];
__device__ float    g_l1[EE*HH];     // logits1 -> overwritten with exp
__device__ float    g_l2[EE*HH];
__device__ unsigned g_m1[NN*HH];     // order-encoded float max
__device__ unsigned g_m2[NN*HH];
__device__ float    g_s1[NN*HH];
__device__ float    g_s2[NN*HH];
__device__ float    g_xgat[NN*CC];
__device__ double   g_sum[CC];
__device__ double   g_sumsq[CC];
__device__ float    g_mu[CC];
__device__ float    g_rstd[CC];
__device__ int      g_degb[NN];
__device__ float    g_acc[NN*CC];
__device__ float    g_o1[NN*CC];
__device__ float    g_attr[NN*CC];
__device__ float    g_xh[(size_t)E2*CC];

// ---------------- helpers ----------------
__device__ __forceinline__ unsigned fenc(float f) {
    unsigned u = __float_as_uint(f);
    return (u & 0x80000000u) ? ~u : (u | 0x80000000u);
}
__device__ __forceinline__ float fdec(unsigned u) {
    return (u & 0x80000000u) ? __uint_as_float(u & 0x7FFFFFFFu) : __uint_as_float(~u);
}

// ---------------- zero scratch ----------------
__global__ void zero_kernel() {
    int i = blockIdx.x * blockDim.x + threadIdx.x;
    int stride = gridDim.x * blockDim.x;
    for (int j = i; j < NN*HH; j += stride) { g_m1[j]=0u; g_m2[j]=0u; g_s1[j]=0.f; g_s2[j]=0.f; }
    for (int j = i; j < NN*CC; j += stride) { g_xgat[j]=0.f; g_acc[j]=0.f; }
    for (int j = i; j < NN;    j += stride) { g_degb[j]=0; }
    if (i < CC) { g_sum[i]=0.0; g_sumsq[i]=0.0; }
}

__global__ void transpose_we2(const float* __restrict__ We2) {
    int i = blockIdx.x * blockDim.x + threadIdx.x;
    if (i < DINF*HC) {
        int f = i >> 7, o = i & 127;
        g_we2t[o*DINF + f] = We2[i];
    }
}

// ---------------- double-buffered register-tiled SGEMM ----------------
// C[M,N] = A[M,K] @ W[K,N] (+ bias), K % BK == 0, N % BN == 0
template<int BM, int BN, int BK, int TM, int TN>
__global__ void __launch_bounds__((BM/TM)*(BN/TN), 2)
gemm_bias(const float* __restrict__ A, const float* __restrict__ W,
          const float* __restrict__ bias, float* __restrict__ C,
          int M, int N, int K) {
    constexpr int THREADS = (BM/TM)*(BN/TN);
    constexpr int A4 = BM*BK/4;
    constexpr int W4 = BK*BN/4;
    constexpr int AI = (A4 + THREADS - 1)/THREADS;
    constexpr int WI = (W4 + THREADS - 1)/THREADS;
    __shared__ float As[2][BK][BM+4];
    __shared__ float Ws[2][BK][BN];
    const int tid  = threadIdx.x;
    const int brow = blockIdx.y * BM;
    const int bcol = blockIdx.x * BN;
    const int trow = (tid / (BN/TN)) * TM;
    const int tcol = (tid % (BN/TN)) * TN;

    float4 stA[AI];
    float4 stW[WI];

    auto loadg = [&](int k0) {
        #pragma unroll
        for (int it = 0; it < AI; it++) {
            int i = tid + it*THREADS;
            if (i < A4) {
                int m = i / (BK/4), k4 = i % (BK/4);
                int gm = brow + m;
                stA[it] = (gm < M) ? *(const float4*)(A + (size_t)gm*K + k0 + k4*4)
                                   : make_float4(0.f,0.f,0.f,0.f);
            }
        }
        #pragma unroll
        for (int it = 0; it < WI; it++) {
            int i = tid + it*THREADS;
            if (i < W4) {
                int kk = i / (BN/4), n4 = i % (BN/4);
                stW[it] = *(const float4*)(W + (size_t)(k0+kk)*N + bcol + n4*4);
            }
        }
    };
    auto store_s = [&](int buf) {
        #pragma unroll
        for (int it = 0; it < AI; it++) {
            int i = tid + it*THREADS;
            if (i < A4) {
                int m = i / (BK/4), k4 = i % (BK/4);
                As[buf][k4*4+0][m] = stA[it].x;
                As[buf][k4*4+1][m] = stA[it].y;
                As[buf][k4*4+2][m] = stA[it].z;
                As[buf][k4*4+3][m] = stA[it].w;
            }
        }
        #pragma unroll
        for (int it = 0; it < WI; it++) {
            int i = tid + it*THREADS;
            if (i < W4) {
                int kk = i / (BN/4), n4 = i % (BN/4);
                *(float4*)&Ws[buf][kk][n4*4] = stW[it];
            }
        }
    };

    float acc[TM][TN];
    #pragma unroll
    for (int i = 0; i < TM; i++)
        #pragma unroll
        for (int j = 0; j < TN; j++) acc[i][j] = 0.f;

    const int nt = K / BK;
    loadg(0);
    store_s(0);
    __syncthreads();

    for (int t = 0; t < nt; t++) {
        int cur = t & 1;
        if (t + 1 < nt) loadg((t+1)*BK);
        #pragma unroll
        for (int kk = 0; kk < BK; kk++) {
            float ra[TM], rb[TN];
            #pragma unroll
            for (int i = 0; i < TM; i += 4)
                *(float4*)&ra[i] = *(const float4*)&As[cur][kk][trow + i];
            #pragma unroll
            for (int j = 0; j < TN; j += 4)
                *(float4*)&rb[j] = *(const float4*)&Ws[cur][kk][tcol + j];
            #pragma unroll
            for (int i = 0; i < TM; i++)
                #pragma unroll
                for (int j = 0; j < TN; j++)
                    acc[i][j] = fmaf(ra[i], rb[j], acc[i][j]);
        }
        if (t + 1 < nt) {
            store_s((t+1) & 1);
            __syncthreads();
        }
    }

    #pragma unroll
    for (int i = 0; i < TM; i++) {
        int gm = brow + trow + i;
        if (gm >= M) continue;
        #pragma unroll
        for (int j = 0; j < TN; j += 4) {
            int gn = bcol + tcol + j;
            float4 v;
            v.x = acc[i][j+0] + (bias ? bias[gn+0] : 0.f);
            v.y = acc[i][j+1] + (bias ? bias[gn+1] : 0.f);
            v.z = acc[i][j+2] + (bias ? bias[gn+2] : 0.f);
            v.w = acc[i][j+3] + (bias ? bias[gn+3] : 0.f);
            *(float4*)(C + (size_t)gm*N + gn) = v;
        }
    }
}

// ---------------- u precompute: u[n,h,f] = sum_c We2[f,h*32+c] * q[n,h,c] ----------------
#define GN 32
__global__ void compute_u() {
    extern __shared__ float shm[];
    float (*sW)[132] = (float (*)[132])shm;               // [out=128][f=128] padded
    float (*sq)[128] = (float (*)[128])(shm + 128*132);   // [GN][128]
    int tid = threadIdx.x;
    int n0 = blockIdx.x * GN;
    for (int i = tid; i < 128*128; i += 256) {
        int o = i >> 7, f = i & 127;
        sW[o][f] = g_we2t[i];
    }
    for (int i = tid; i < GN*128; i += 256) {
        int nl = i >> 7, c = i & 127;
        int n = n0 + nl;
        sq[nl][c] = (n < NN) ? g_q[(size_t)n*128 + c] : 0.f;
    }
    __syncthreads();
    int w = tid >> 5, lane = tid & 31;
    for (int p = w; p < GN*HH; p += 8) {
        int nl = p >> 2, h = p & 3;
        int n = n0 + nl;
        if (n >= NN) continue;
        float a0=0.f, a1=0.f, a2=0.f, a3=0.f;
        #pragma unroll
        for (int c = 0; c < 32; c++) {
            float qv = sq[nl][h*32 + c];
            const float* row = sW[h*32 + c];
            a0 = fmaf(qv, row[lane],      a0);
            a1 = fmaf(qv, row[lane + 32], a1);
            a2 = fmaf(qv, row[lane + 64], a2);
            a3 = fmaf(qv, row[lane + 96], a3);
        }
        size_t base = (size_t)n*512 + h*128;
        g_u[base + lane]      = a0;
        g_u[base + lane + 32] = a1;
        g_u[base + lane + 64] = a2;
        g_u[base + lane + 96] = a3;
    }
}

// ---------------- attention pass 1: logits + segment max (warp per edge) ----------------
__global__ void attn_logits(const int* __restrict__ ei, const float* __restrict__ ea,
                            const float* __restrict__ be2) {
    int e = (blockIdx.x * blockDim.x + threadIdx.x) >> 5;
    if (e >= EE) return;
    int lane = threadIdx.x & 31;
    int s = ei[e], d = ei[EE + e];
    const float scale = 0.17677669529663687f;  // 1/sqrt(32)
    float r0 = ea[(size_t)e*128 + lane];
    float r1 = ea[(size_t)e*128 + lane + 32];
    float r2 = ea[(size_t)e*128 + lane + 64];
    float r3 = ea[(size_t)e*128 + lane + 96];
    #pragma unroll
    for (int h = 0; h < HH; h++) {
        float qv = g_q[d*HC + h*32 + lane];
        float kv = g_k[s*HC + h*32 + lane];
        float p1 = qv * kv;
        float p2 = qv * be2[h*32 + lane];
        const float* up = g_u + (size_t)d*512 + h*128;
        p2 = fmaf(r0, up[lane],      p2);
        p2 = fmaf(r1, up[lane + 32], p2);
        p2 = fmaf(r2, up[lane + 64], p2);
        p2 = fmaf(r3, up[lane + 96], p2);
        #pragma unroll
        for (int o = 16; o > 0; o >>= 1) {
            p1 += __shfl_xor_sync(0xffffffffu, p1, o);
            p2 += __shfl_xor_sync(0xffffffffu, p2, o);
        }
        if (lane == h) {
            float l1 = p1 * scale, l2 = p2 * scale;
            g_l1[e*HH + h] = l1;
            g_l2[e*HH + h] = l2;
            atomicMax(&g_m1[d*HH + h], fenc(l1));
            atomicMax(&g_m2[d*HH + h], fenc(l2));
        }
    }
}

// ---------------- attention pass 2: exp + segment sum ----------------
__global__ void attn_exp(const int* __restrict__ ei) {
    int idx = blockIdx.x * blockDim.x + threadIdx.x;
    if (idx >= EE*HH) return;
    int e = idx >> 2, h = idx & 3;
    int d = ei[EE + e];
    float m1 = fdec(g_m1[d*HH + h]);
    float m2 = fdec(g_m2[d*HH + h]);
    float ex1 = __expf(g_l1[idx] - m1);
    float ex2 = __expf(g_l2[idx] - m2);
    g_l1[idx] = ex1;
    g_l2[idx] = ex2;
    atomicAdd(&g_s1[d*HH + h], ex1);
    atomicAdd(&g_s2[d*HH + h], ex2);
}

// ---------------- attention pass 3: msg @ Wcon + scatter (warp per edge) ----------------
__global__ void attn_msg(const int* __restrict__ ei, const float* __restrict__ Wcon) {
    __shared__ float sW[HC][CC];
    __shared__ float smsg[8][HC];
    int tid = threadIdx.x;
    for (int i = tid; i < HC*CC; i += 256) sW[i / CC][i % CC] = Wcon[i];
    __syncthreads();
    int w = tid >> 5, lane = tid & 31;
    int e = blockIdx.x * 8 + w;
    if (e < EE) {
        int s = ei[e], d = ei[EE + e];
        #pragma unroll
        for (int h = 0; h < HH; h++) {
            float a1 = g_l1[e*HH + h] / (g_s1[d*HH + h] + 1e-16f);
            float a2 = g_l2[e*HH + h] / (g_s2[d*HH + h] + 1e-16f);
            float msgk = g_v[s*HC + h*32 + lane] * a1
                       + g_ea3[(size_t)e*HC + h*32 + lane] * a2;
            smsg[w][h*32 + lane] = msgk;
        }
        __syncwarp();
        float out = 0.f;
        #pragma unroll
        for (int kk = 0; kk < HC; kk++)
            out = fmaf(smsg[w][kk], sW[kk][lane], out);
        atomicAdd(&g_xgat[d*CC + lane], out);
    }
}

// ---------------- BatchNorm stats / finalize / apply+GELU ----------------
__global__ void bn_stats() {
    __shared__ float ssum[8][CC], ssq[8][CC];
    int c  = threadIdx.x & 31;
    int ry = threadIdx.x >> 5;
    float s = 0.f, q = 0.f;
    for (int r = blockIdx.x * 8 + ry; r < NN; r += gridDim.x * 8) {
        float v = g_xgat[r*CC + c];
        s += v; q += v * v;
    }
    ssum[ry][c] = s; ssq[ry][c] = q;
    __syncthreads();
    if (ry == 0) {
        #pragma unroll
        for (int i = 1; i < 8; i++) { s += ssum[i][c]; q += ssq[i][c]; }
        atomicAdd(&g_sum[c],   (double)s);
        atomicAdd(&g_sumsq[c], (double)q);
    }
}

__global__ void bn_final() {
    int c = threadIdx.x;
    if (c < CC) {
        double mu  = g_sum[c] / (double)NN;
        double var = g_sumsq[c] / (double)NN - mu * mu;
        g_mu[c]   = (float)mu;
        g_rstd[c] = (float)(1.0 / sqrt(var + 1e-5));
    }
}

__global__ void bn_apply(const float* __restrict__ bn_w, const float* __restrict__ bn_b,
                         float* __restrict__ out1) {
    int i = blockIdx.x * blockDim.x + threadIdx.x;
    if (i >= NN*CC) return;
    int c = i & 31;
    float xn = bn_w[c] * (g_xgat[i] - g_mu[c]) * g_rstd[c] + bn_b[c];
    out1[i] = 0.5f * xn * (1.0f + erff(xn * 0.70710678118654752f));
}

// ---------------- hypergraph branch ----------------
__global__ void hyper_deg(const int* __restrict__ ei) {
    int i = blockIdx.x * blockDim.x + threadIdx.x;
    if (i >= E2) return;
    atomicAdd(&g_degb[ei[i]],      1);
    atomicAdd(&g_degb[ei[EE + i]], 1);
}

__global__ void hyper_acc(const int* __restrict__ ei) {
    int idx = blockIdx.x * blockDim.x + threadIdx.x;
    if (idx >= E2*CC) return;
    int i = idx >> 5, c = idx & 31;
    float xv = g_xh[idx];
    atomicAdd(&g_acc[ei[i]*CC + c],      xv);
    atomicAdd(&g_acc[ei[EE + i]*CC + c], xv);
}

__global__ void hyper_o1() {
    int idx = blockIdx.x * blockDim.x + threadIdx.x;
    if (idx >= NN*CC) return;
    int n = idx >> 5;
    int deg = g_degb[n];
    float binv = (deg > 0) ? (1.0f / (float)deg) : 0.f;
    g_o1[idx] = g_acc[idx] * binv + g_attr[idx];
}

__global__ void hyper_out(const int* __restrict__ ei, const float* __restrict__ bh,
                          float* __restrict__ out2) {
    int idx = blockIdx.x * blockDim.x + threadIdx.x;
    if (idx >= E2*CC) return;
    int i = idx >> 5, c = idx & 31;
    out2[idx] = 0.5f * (g_o1[ei[i]*CC + c] + g_o1[ei[EE + i]*CC + c]) + bh[c];
}

// ---------------- launcher ----------------
extern "C" void kernel_launch(void* const* d_in, const int* in_sizes, int n_in,
                              void* d_out, int out_size) {
    const float* x    = (const float*)d_in[0];
    const float* ea   = (const float*)d_in[1];
    const float* Wq   = (const float*)d_in[2];
    const float* bq   = (const float*)d_in[3];
    const float* Wk   = (const float*)d_in[4];
    const float* bk   = (const float*)d_in[5];
    const float* Wv   = (const float*)d_in[6];
    const float* bv   = (const float*)d_in[7];
    const float* We2  = (const float*)d_in[8];
    const float* be2  = (const float*)d_in[9];
    const float* We3  = (const float*)d_in[10];
    const float* be3  = (const float*)d_in[11];
    const float* Wcon = (const float*)d_in[12];
    const float* bn_w = (const float*)d_in[13];
    const float* bn_b = (const float*)d_in[14];
    const float* Wh1  = (const float*)d_in[15];
    const float* Wh2  = (const float*)d_in[16];
    const float* bh   = (const float*)d_in[17];
    const int*   ei   = (const int*)d_in[18];

    float* out  = (float*)d_out;
    float* out1 = out;                       // x_gat: NN*CC
    float* out2 = out + (size_t)NN * CC;     // edge_attr2: E2*CC

    float *pq, *pk, *pv, *pea3, *pattr, *pxh;
    cudaGetSymbolAddress((void**)&pq,    g_q);
    cudaGetSymbolAddress((void**)&pk,    g_k);
    cudaGetSymbolAddress((void**)&pv,    g_v);
    cudaGetSymbolAddress((void**)&pea3,  g_ea3);
    cudaGetSymbolAddress((void**)&pattr, g_attr);
    cudaGetSymbolAddress((void**)&pxh,   g_xh);

    const int U_SMEM = (128*132 + GN*128) * 4;
    cudaFuncSetAttribute(compute_u, cudaFuncAttributeMaxDynamicSharedMemorySize, U_SMEM);

    zero_kernel<<<512, 256>>>();
    transpose_we2<<<64, 256>>>(We2);

    // node projections: [50000,128] @ [128,128]
    dim3 gN(1, (NN + 127) / 128);
    gemm_bias<128,128,16,8,8><<<gN, 256>>>(x, Wq, bq, pq, NN, HC, DINF);
    gemm_bias<128,128,16,8,8><<<gN, 256>>>(x, Wk, bk, pk, NN, HC, DINF);
    gemm_bias<128,128,16,8,8><<<gN, 256>>>(x, Wv, bv, pv, NN, HC, DINF);

    // u precompute (replaces ea2 GEMM)
    compute_u<<<(NN + GN - 1)/GN, 256, U_SMEM>>>();

    // edge projection: only ea3 now
    dim3 gE(1, EE / 128);
    gemm_bias<128,128,16,8,8><<<gE, 256>>>(ea, We3, be3, pea3, EE, HC, DINF);

    // attention: logits + max, exp + sum, msg + scatter
    attn_logits<<<EE / 8, 256>>>(ei, ea, be2);
    attn_exp<<<(EE * HH + 255) / 256, 256>>>(ei);
    attn_msg<<<EE / 8, 256>>>(ei, Wcon);

    // batchnorm + gelu -> out1
    bn_stats<<<256, 256>>>();
    bn_final<<<1, 32>>>();
    bn_apply<<<(NN * CC + 255) / 256, 256>>>(bn_w, bn_b, out1);

    // hypergraph branch
    gemm_bias<128,32,16,4,4><<<dim3(1, (NN + 127) / 128), 256>>>(x,  Wh2, nullptr, pattr, NN, CC, DINF);
    gemm_bias<128,32,16,4,4><<<dim3(1, E2 / 128),         256>>>(ea, Wh1, nullptr, pxh,  E2, CC, DINF);
    hyper_deg<<<(E2 + 255) / 256, 256>>>(ei);
    hyper_acc<<<(E2 * CC + 255) / 256, 256>>>(ei);
    hyper_o1<<<(NN * CC + 255) / 256, 256>>>();
    hyper_out<<<(E2 * CC + 255) / 256, 256>>>(ei, bh, out2);
}

// round 3
// speedup vs baseline: 2.7630x; 1.4932x over previous
#include <cuda_runtime.h>
#include <math.h>
#include <stdint.h>

#define NN 50000
#define EE 512000
#define E2 (EE/2)
#define DINF 128
#define HC 128
#define CC 32
#define HH 4
#define AYW 656   // 128 va | 512 y | 1 ind | 15 pad

// ---------------- scratch (device globals; no allocations allowed) ----------------
__device__ float    g_q[NN*HC];
__device__ float    g_k[NN*HC];
__device__ float    g_v[NN*HC];
__device__ float    g_u[(size_t)NN*HH*DINF];   // u[n][h][f]
__device__ float    g_we2t[DINF*HC];           // We2 transposed: [out][f]
__device__ float    g_l1[EE*HH];               // logits1 -> overwritten with exp
__device__ float    g_l2[EE*HH];
__device__ unsigned g_m1[NN*HH];               // order-encoded float max
__device__ unsigned g_m2[NN*HH];
__device__ float    g_s1[NN*HH];
__device__ float    g_s2[NN*HH];
__device__ float    g_ay[(size_t)NN*AYW];      // [va | y | ind | pad]
__device__ float    g_axh[(size_t)NN*256];     // [se_scaled | x]
__device__ float    g_wbig[AYW*CC];            // [Wcon; Wfold; bc; 0]
__device__ float    g_wh[256*CC];              // [Wh1; Wh2]
__device__ float    g_xgat[NN*CC];
__device__ float    g_o1[NN*CC];
__device__ double   g_sum[CC];
__device__ double   g_sumsq[CC];
__device__ float    g_mu[CC];
__device__ float    g_rstd[CC];
// CSR
__device__ int      g_cntA[NN];
__device__ int      g_cntH[NN];
__device__ int      g_offA[NN+1];
__device__ int      g_offH[NN+1];
__device__ int      g_curA[NN];
__device__ int      g_curH[NN];
__device__ int      g_payA[EE];
__device__ int      g_payH[EE];   // 2*E2 = EE/ ... actually 2*E2 = 512000 entries

// ---------------- helpers ----------------
__device__ __forceinline__ unsigned fenc(float f) {
    unsigned u = __float_as_uint(f);
    return (u & 0x80000000u) ? ~u : (u | 0x80000000u);
}
__device__ __forceinline__ float fdec(unsigned u) {
    return (u & 0x80000000u) ? __uint_as_float(u & 0x7FFFFFFFu) : __uint_as_float(~u);
}

// ---------------- zero scratch ----------------
__global__ void zero_kernel() {
    int i = blockIdx.x * blockDim.x + threadIdx.x;
    int stride = gridDim.x * blockDim.x;
    for (int j = i; j < NN*HH; j += stride) { g_m1[j]=0u; g_m2[j]=0u; g_s1[j]=0.f; g_s2[j]=0.f; }
    for (int j = i; j < NN;    j += stride) { g_cntA[j]=0; g_cntH[j]=0; }
    if (i < CC) { g_sum[i]=0.0; g_sumsq[i]=0.0; }
}

__global__ void transpose_we2(const float* __restrict__ We2) {
    int i = blockIdx.x * blockDim.x + threadIdx.x;
    if (i < DINF*HC) {
        int f = i >> 7, o = i & 127;
        g_we2t[o*DINF + f] = We2[i];
    }
}

// ---------------- weight prep: Wbig = [Wcon; We3@Wcon per-head; bc; 0], Wh = [Wh1; Wh2] ----------------
__global__ void prep_weights(const float* __restrict__ Wcon, const float* __restrict__ We3,
                             const float* __restrict__ be3,
                             const float* __restrict__ Wh1, const float* __restrict__ Wh2) {
    int idx = blockIdx.x * blockDim.x + threadIdx.x;
    int total = AYW*CC + 256*CC;
    if (idx >= total) return;
    if (idx < AYW*CC) {
        int r = idx / CC, c = idx % CC;
        float v;
        if (r < 128) {
            v = Wcon[r*CC + c];
        } else if (r < 640) {
            int h = (r - 128) >> 7, f = (r - 128) & 127;
            float a = 0.f;
            #pragma unroll
            for (int c2 = 0; c2 < 32; c2++)
                a = fmaf(We3[f*HC + h*32 + c2], Wcon[(h*32 + c2)*CC + c], a);
            v = a;
        } else if (r == 640) {
            float a = 0.f;
            for (int k = 0; k < HC; k++)
                a = fmaf(be3[k], Wcon[k*CC + c], a);
            v = a;
        } else v = 0.f;
        g_wbig[r*CC + c] = v;
    } else {
        int j = idx - AYW*CC;
        int r = j / CC, c = j % CC;
        g_wh[r*CC + c] = (r < 128) ? Wh1[r*CC + c] : Wh2[(r-128)*CC + c];
    }
}

// ---------------- CSR build ----------------
__global__ void csr_count(const int* __restrict__ ei) {
    int i = blockIdx.x * blockDim.x + threadIdx.x;
    if (i >= EE) return;
    atomicAdd(&g_cntA[ei[EE + i]], 1);
    if (i < E2) {
        atomicAdd(&g_cntH[ei[i]],      1);
        atomicAdd(&g_cntH[ei[EE + i]], 1);
    }
}

__global__ void scan_kernel(const int* __restrict__ cnt, int* __restrict__ off,
                            int* __restrict__ cur, int n) {
    __shared__ int sdata[1024];
    __shared__ int s_running;
    if (threadIdx.x == 0) s_running = 0;
    __syncthreads();
    for (int base = 0; base < n; base += 1024) {
        int i = base + threadIdx.x;
        int v = (i < n) ? cnt[i] : 0;
        sdata[threadIdx.x] = v;
        __syncthreads();
        #pragma unroll
        for (int ofs = 1; ofs < 1024; ofs <<= 1) {
            int t = (threadIdx.x >= ofs) ? sdata[threadIdx.x - ofs] : 0;
            __syncthreads();
            sdata[threadIdx.x] += t;
            __syncthreads();
        }
        int excl = sdata[threadIdx.x] - v;
        if (i < n) { off[i] = s_running + excl; cur[i] = s_running + excl; }
        int total = sdata[1023];
        __syncthreads();
        if (threadIdx.x == 0) s_running += total;
        __syncthreads();
    }
    if (threadIdx.x == 0) off[n] = s_running;
}

__global__ void csr_fill(const int* __restrict__ ei) {
    int i = blockIdx.x * blockDim.x + threadIdx.x;
    if (i >= EE) return;
    int d = ei[EE + i];
    int pos = atomicAdd(&g_curA[d], 1);
    g_payA[pos] = i;
    if (i < E2) {
        int p1 = atomicAdd(&g_curH[ei[i]], 1);
        g_payH[p1] = i;
        int p2 = atomicAdd(&g_curH[ei[EE + i]], 1);
        g_payH[p2] = i;
    }
}

// ---------------- double-buffered register-tiled SGEMM ----------------
template<int BM, int BN, int BK, int TM, int TN>
__global__ void __launch_bounds__((BM/TM)*(BN/TN), 2)
gemm_bias(const float* __restrict__ A, const float* __restrict__ W,
          const float* __restrict__ bias, float* __restrict__ C,
          int M, int N, int K) {
    constexpr int THREADS = (BM/TM)*(BN/TN);
    constexpr int A4 = BM*BK/4;
    constexpr int W4 = BK*BN/4;
    constexpr int AI = (A4 + THREADS - 1)/THREADS;
    constexpr int WI = (W4 + THREADS - 1)/THREADS;
    __shared__ float As[2][BK][BM+4];
    __shared__ float Ws[2][BK][BN];
    const int tid  = threadIdx.x;
    const int brow = blockIdx.y * BM;
    const int bcol = blockIdx.x * BN;
    const int trow = (tid / (BN/TN)) * TM;
    const int tcol = (tid % (BN/TN)) * TN;

    float4 stA[AI];
    float4 stW[WI];

    auto loadg = [&](int k0) {
        #pragma unroll
        for (int it = 0; it < AI; it++) {
            int i = tid + it*THREADS;
            if (i < A4) {
                int m = i / (BK/4), k4 = i % (BK/4);
                int gm = brow + m;
                stA[it] = (gm < M) ? *(const float4*)(A + (size_t)gm*K + k0 + k4*4)
                                   : make_float4(0.f,0.f,0.f,0.f);
            }
        }
        #pragma unroll
        for (int it = 0; it < WI; it++) {
            int i = tid + it*THREADS;
            if (i < W4) {
                int kk = i / (BN/4), n4 = i % (BN/4);
                stW[it] = *(const float4*)(W + (size_t)(k0+kk)*N + bcol + n4*4);
            }
        }
    };
    auto store_s = [&](int buf) {
        #pragma unroll
        for (int it = 0; it < AI; it++) {
            int i = tid + it*THREADS;
            if (i < A4) {
                int m = i / (BK/4), k4 = i % (BK/4);
                As[buf][k4*4+0][m] = stA[it].x;
                As[buf][k4*4+1][m] = stA[it].y;
                As[buf][k4*4+2][m] = stA[it].z;
                As[buf][k4*4+3][m] = stA[it].w;
            }
        }
        #pragma unroll
        for (int it = 0; it < WI; it++) {
            int i = tid + it*THREADS;
            if (i < W4) {
                int kk = i / (BN/4), n4 = i % (BN/4);
                *(float4*)&Ws[buf][kk][n4*4] = stW[it];
            }
        }
    };

    float acc[TM][TN];
    #pragma unroll
    for (int i = 0; i < TM; i++)
        #pragma unroll
        for (int j = 0; j < TN; j++) acc[i][j] = 0.f;

    const int nt = K / BK;
    loadg(0);
    store_s(0);
    __syncthreads();

    for (int t = 0; t < nt; t++) {
        int cur = t & 1;
        if (t + 1 < nt) loadg((t+1)*BK);
        #pragma unroll
        for (int kk = 0; kk < BK; kk++) {
            float ra[TM], rb[TN];
            #pragma unroll
            for (int i = 0; i < TM; i += 4)
                *(float4*)&ra[i] = *(const float4*)&As[cur][kk][trow + i];
            #pragma unroll
            for (int j = 0; j < TN; j += 4)
                *(float4*)&rb[j] = *(const float4*)&Ws[cur][kk][tcol + j];
            #pragma unroll
            for (int i = 0; i < TM; i++)
                #pragma unroll
                for (int j = 0; j < TN; j++)
                    acc[i][j] = fmaf(ra[i], rb[j], acc[i][j]);
        }
        if (t + 1 < nt) {
            store_s((t+1) & 1);
            __syncthreads();
        }
    }

    #pragma unroll
    for (int i = 0; i < TM; i++) {
        int gm = brow + trow + i;
        if (gm >= M) continue;
        #pragma unroll
        for (int j = 0; j < TN; j += 4) {
            int gn = bcol + tcol + j;
            float4 v;
            v.x = acc[i][j+0] + (bias ? bias[gn+0] : 0.f);
            v.y = acc[i][j+1] + (bias ? bias[gn+1] : 0.f);
            v.z = acc[i][j+2] + (bias ? bias[gn+2] : 0.f);
            v.w = acc[i][j+3] + (bias ? bias[gn+3] : 0.f);
            *(float4*)(C + (size_t)gm*N + gn) = v;
        }
    }
}

// ---------------- u precompute: u[n,h,f] = sum_c We2[f,h*32+c] * q[n,h,c] ----------------
#define GN 32
__global__ void compute_u() {
    extern __shared__ float shm[];
    float (*sW)[132] = (float (*)[132])shm;               // [out=128][f=128] padded
    float (*sq)[128] = (float (*)[128])(shm + 128*132);   // [GN][128]
    int tid = threadIdx.x;
    int n0 = blockIdx.x * GN;
    for (int i = tid; i < 128*128; i += 256) {
        int o = i >> 7, f = i & 127;
        sW[o][f] = g_we2t[i];
    }
    for (int i = tid; i < GN*128; i += 256) {
        int nl = i >> 7, c = i & 127;
        int n = n0 + nl;
        sq[nl][c] = (n < NN) ? g_q[(size_t)n*128 + c] : 0.f;
    }
    __syncthreads();
    int w = tid >> 5, lane = tid & 31;
    for (int p = w; p < GN*HH; p += 8) {
        int nl = p >> 2, h = p & 3;
        int n = n0 + nl;
        if (n >= NN) continue;
        float a0=0.f, a1=0.f, a2=0.f, a3=0.f;
        #pragma unroll
        for (int c = 0; c < 32; c++) {
            float qv = sq[nl][h*32 + c];
            const float* row = sW[h*32 + c];
            a0 = fmaf(qv, row[lane],      a0);
            a1 = fmaf(qv, row[lane + 32], a1);
            a2 = fmaf(qv, row[lane + 64], a2);
            a3 = fmaf(qv, row[lane + 96], a3);
        }
        size_t base = (size_t)n*512 + h*128;
        g_u[base + lane]      = a0;
        g_u[base + lane + 32] = a1;
        g_u[base + lane + 64] = a2;
        g_u[base + lane + 96] = a3;
    }
}

// ---------------- attention pass 1: logits + segment max (warp per edge) ----------------
__global__ void attn_logits(const int* __restrict__ ei, const float* __restrict__ ea,
                            const float* __restrict__ be2) {
    int e = (blockIdx.x * blockDim.x + threadIdx.x) >> 5;
    if (e >= EE) return;
    int lane = threadIdx.x & 31;
    int s = ei[e], d = ei[EE + e];
    const float scale = 0.17677669529663687f;  // 1/sqrt(32)
    float r0 = ea[(size_t)e*128 + lane];
    float r1 = ea[(size_t)e*128 + lane + 32];
    float r2 = ea[(size_t)e*128 + lane + 64];
    float r3 = ea[(size_t)e*128 + lane + 96];
    #pragma unroll
    for (int h = 0; h < HH; h++) {
        float qv = g_q[d*HC + h*32 + lane];
        float kv = g_k[s*HC + h*32 + lane];
        float p1 = qv * kv;
        float p2 = qv * be2[h*32 + lane];
        const float* up = g_u + (size_t)d*512 + h*128;
        p2 = fmaf(r0, up[lane],      p2);
        p2 = fmaf(r1, up[lane + 32], p2);
        p2 = fmaf(r2, up[lane + 64], p2);
        p2 = fmaf(r3, up[lane + 96], p2);
        #pragma unroll
        for (int o = 16; o > 0; o >>= 1) {
            p1 += __shfl_xor_sync(0xffffffffu, p1, o);
            p2 += __shfl_xor_sync(0xffffffffu, p2, o);
        }
        if (lane == h) {
            float l1 = p1 * scale, l2 = p2 * scale;
            g_l1[e*HH + h] = l1;
            g_l2[e*HH + h] = l2;
            atomicMax(&g_m1[d*HH + h], fenc(l1));
            atomicMax(&g_m2[d*HH + h], fenc(l2));
        }
    }
}

// ---------------- attention pass 2: exp + segment sum ----------------
__global__ void attn_exp(const int* __restrict__ ei) {
    int idx = blockIdx.x * blockDim.x + threadIdx.x;
    if (idx >= EE*HH) return;
    int e = idx >> 2, h = idx & 3;
    int d = ei[EE + e];
    float m1 = fdec(g_m1[d*HH + h]);
    float m2 = fdec(g_m2[d*HH + h]);
    float ex1 = __expf(g_l1[idx] - m1);
    float ex2 = __expf(g_l2[idx] - m2);
    g_l1[idx] = ex1;
    g_l2[idx] = ex2;
    atomicAdd(&g_s1[d*HH + h], ex1);
    atomicAdd(&g_s2[d*HH + h], ex2);
}

// ---------------- attention aggregation (warp per dst node, CSR) ----------------
__global__ void aggregate_attn(const int* __restrict__ ei, const float* __restrict__ ea) {
    int w = (blockIdx.x * blockDim.x + threadIdx.x) >> 5;
    if (w >= NN) return;
    int lane = threadIdx.x & 31;
    int d = w;
    int beg = g_offA[d], end = g_offA[d+1];
    int hsel = lane >> 3;
    float4 va = make_float4(0.f,0.f,0.f,0.f);
    float4 y0 = va, y1 = va, y2 = va, y3 = va;
    for (int idx = beg; idx < end; idx++) {
        int e = g_payA[idx];
        int s = ei[e];
        float4 ex1 = *(const float4*)&g_l1[e*4];
        float4 ex2 = *(const float4*)&g_l2[e*4];
        float4 eav = *(const float4*)&ea[(size_t)e*128 + lane*4];
        float4 vv  = *(const float4*)&g_v[(size_t)s*128 + lane*4];
        y0.x = fmaf(ex2.x, eav.x, y0.x); y0.y = fmaf(ex2.x, eav.y, y0.y);
        y0.z = fmaf(ex2.x, eav.z, y0.z); y0.w = fmaf(ex2.x, eav.w, y0.w);
        y1.x = fmaf(ex2.y, eav.x, y1.x); y1.y = fmaf(ex2.y, eav.y, y1.y);
        y1.z = fmaf(ex2.y, eav.z, y1.z); y1.w = fmaf(ex2.y, eav.w, y1.w);
        y2.x = fmaf(ex2.z, eav.x, y2.x); y2.y = fmaf(ex2.z, eav.y, y2.y);
        y2.z = fmaf(ex2.z, eav.z, y2.z); y2.w = fmaf(ex2.z, eav.w, y2.w);
        y3.x = fmaf(ex2.w, eav.x, y3.x); y3.y = fmaf(ex2.w, eav.y, y3.y);
        y3.z = fmaf(ex2.w, eav.z, y3.z); y3.w = fmaf(ex2.w, eav.w, y3.w);
        float e1 = (hsel == 0) ? ex1.x : (hsel == 1) ? ex1.y : (hsel == 2) ? ex1.z : ex1.w;
        va.x = fmaf(e1, vv.x, va.x); va.y = fmaf(e1, vv.y, va.y);
        va.z = fmaf(e1, vv.z, va.z); va.w = fmaf(e1, vv.w, va.w);
    }
    float4 s1 = *(const float4*)&g_s1[d*4];
    float4 s2 = *(const float4*)&g_s2[d*4];
    float r1 = 1.f / (((hsel==0)?s1.x:(hsel==1)?s1.y:(hsel==2)?s1.z:s1.w) + 1e-16f);
    va.x *= r1; va.y *= r1; va.z *= r1; va.w *= r1;
    float q0 = 1.f/(s2.x+1e-16f), q1 = 1.f/(s2.y+1e-16f), q2 = 1.f/(s2.z+1e-16f), q3 = 1.f/(s2.w+1e-16f);
    y0.x*=q0; y0.y*=q0; y0.z*=q0; y0.w*=q0;
    y1.x*=q1; y1.y*=q1; y1.z*=q1; y1.w*=q1;
    y2.x*=q2; y2.y*=q2; y2.z*=q2; y2.w*=q2;
    y3.x*=q3; y3.y*=q3; y3.z*=q3; y3.w*=q3;
    float* row = g_ay + (size_t)d*AYW;
    *(float4*)&row[lane*4]              = va;
    *(float4*)&row[128 + 0*128 + lane*4] = y0;
    *(float4*)&row[128 + 1*128 + lane*4] = y1;
    *(float4*)&row[128 + 2*128 + lane*4] = y2;
    *(float4*)&row[128 + 3*128 + lane*4] = y3;
    if (lane == 0)      row[640] = (end > beg) ? 1.f : 0.f;
    else if (lane < 16) row[640 + lane] = 0.f;
}

// ---------------- hyper aggregation (warp per node, CSR) ----------------
__global__ void aggregate_hyper(const float* __restrict__ ea) {
    int w = (blockIdx.x * blockDim.x + threadIdx.x) >> 5;
    if (w >= NN) return;
    int lane = threadIdx.x & 31;
    int beg = g_offH[w], end = g_offH[w+1];
    float4 acc = make_float4(0.f,0.f,0.f,0.f);
    for (int idx = beg; idx < end; idx++) {
        int i = g_payH[idx];
        float4 eav = *(const float4*)&ea[(size_t)i*128 + lane*4];
        acc.x += eav.x; acc.y += eav.y; acc.z += eav.z; acc.w += eav.w;
    }
    int len = end - beg;
    float binv = (len > 0) ? (1.f / (float)len) : 0.f;
    acc.x *= binv; acc.y *= binv; acc.z *= binv; acc.w *= binv;
    *(float4*)&g_axh[(size_t)w*256 + lane*4] = acc;
}

__global__ void copy_x(const float* __restrict__ x) {
    int idx = blockIdx.x * blockDim.x + threadIdx.x;
    if (idx >= NN*32) return;
    int n = idx >> 5, c4 = idx & 31;
    *(float4*)&g_axh[(size_t)n*256 + 128 + c4*4] = *(const float4*)&x[(size_t)n*128 + c4*4];
}

// ---------------- BatchNorm stats / finalize / apply+GELU ----------------
__global__ void bn_stats() {
    __shared__ float ssum[8][CC], ssq[8][CC];
    int c  = threadIdx.x & 31;
    int ry = threadIdx.x >> 5;
    float s = 0.f, q = 0.f;
    for (int r = blockIdx.x * 8 + ry; r < NN; r += gridDim.x * 8) {
        float v = g_xgat[r*CC + c];
        s += v; q += v * v;
    }
    ssum[ry][c] = s; ssq[ry][c] = q;
    __syncthreads();
    if (ry == 0) {
        #pragma unroll
        for (int i = 1; i < 8; i++) { s += ssum[i][c]; q += ssq[i][c]; }
        atomicAdd(&g_sum[c],   (double)s);
        atomicAdd(&g_sumsq[c], (double)q);
    }
}

__global__ void bn_final() {
    int c = threadIdx.x;
    if (c < CC) {
        double mu  = g_sum[c] / (double)NN;
        double var = g_sumsq[c] / (double)NN - mu * mu;
        g_mu[c]   = (float)mu;
        g_rstd[c] = (float)(1.0 / sqrt(var + 1e-5));
    }
}

__global__ void bn_apply(const float* __restrict__ bn_w, const float* __restrict__ bn_b,
                         float* __restrict__ out1) {
    int i = blockIdx.x * blockDim.x + threadIdx.x;
    if (i >= NN*CC) return;
    int c = i & 31;
    float xn = bn_w[c] * (g_xgat[i] - g_mu[c]) * g_rstd[c] + bn_b[c];
    out1[i] = 0.5f * xn * (1.0f + erff(xn * 0.70710678118654752f));
}

// ---------------- hyper output ----------------
__global__ void hyper_out(const int* __restrict__ ei, const float* __restrict__ bh,
                          float* __restrict__ out2) {
    int idx = blockIdx.x * blockDim.x + threadIdx.x;
    if (idx >= E2*CC) return;
    int i = idx >> 5, c = idx & 31;
    out2[idx] = 0.5f * (g_o1[ei[i]*CC + c] + g_o1[ei[EE + i]*CC + c]) + bh[c];
}

// ---------------- launcher ----------------
extern "C" void kernel_launch(void* const* d_in, const int* in_sizes, int n_in,
                              void* d_out, int out_size) {
    const float* x    = (const float*)d_in[0];
    const float* ea   = (const float*)d_in[1];
    const float* Wq   = (const float*)d_in[2];
    const float* bq   = (const float*)d_in[3];
    const float* Wk   = (const float*)d_in[4];
    const float* bk   = (const float*)d_in[5];
    const float* Wv   = (const float*)d_in[6];
    const float* bv   = (const float*)d_in[7];
    const float* We2  = (const float*)d_in[8];
    const float* be2  = (const float*)d_in[9];
    const float* We3  = (const float*)d_in[10];
    const float* be3  = (const float*)d_in[11];
    const float* Wcon = (const float*)d_in[12];
    const float* bn_w = (const float*)d_in[13];
    const float* bn_b = (const float*)d_in[14];
    const float* Wh1  = (const float*)d_in[15];
    const float* Wh2  = (const float*)d_in[16];
    const float* bh   = (const float*)d_in[17];
    const int*   ei   = (const int*)d_in[18];

    float* out  = (float*)d_out;
    float* out1 = out;                       // x_gat: NN*CC
    float* out2 = out + (size_t)NN * CC;     // edge_attr2: E2*CC

    float *pq, *pk, *pv, *pay, *paxh, *pwbig, *pwh, *pxgat, *po1;
    int *pcntA, *pcntH, *poffA, *poffH, *pcurA, *pcurH;
    cudaGetSymbolAddress((void**)&pq,    g_q);
    cudaGetSymbolAddress((void**)&pk,    g_k);
    cudaGetSymbolAddress((void**)&pv,    g_v);
    cudaGetSymbolAddress((void**)&pay,   g_ay);
    cudaGetSymbolAddress((void**)&paxh,  g_axh);
    cudaGetSymbolAddress((void**)&pwbig, g_wbig);
    cudaGetSymbolAddress((void**)&pwh,   g_wh);
    cudaGetSymbolAddress((void**)&pxgat, g_xgat);
    cudaGetSymbolAddress((void**)&po1,   g_o1);
    cudaGetSymbolAddress((void**)&pcntA, g_cntA);
    cudaGetSymbolAddress((void**)&pcntH, g_cntH);
    cudaGetSymbolAddress((void**)&poffA, g_offA);
    cudaGetSymbolAddress((void**)&poffH, g_offH);
    cudaGetSymbolAddress((void**)&pcurA, g_curA);
    cudaGetSymbolAddress((void**)&pcurH, g_curH);

    const int U_SMEM = (128*132 + GN*128) * 4;
    cudaFuncSetAttribute(compute_u, cudaFuncAttributeMaxDynamicSharedMemorySize, U_SMEM);

    zero_kernel<<<512, 256>>>();
    transpose_we2<<<64, 256>>>(We2);
    prep_weights<<<(AYW*CC + 256*CC + 255)/256, 256>>>(Wcon, We3, be3, Wh1, Wh2);

    // CSR build
    csr_count<<<(EE + 255)/256, 256>>>(ei);
    scan_kernel<<<1, 1024>>>(pcntA, poffA, pcurA, NN);
    scan_kernel<<<1, 1024>>>(pcntH, poffH, pcurH, NN);
    csr_fill<<<(EE + 255)/256, 256>>>(ei);

    // node projections: [50000,128] @ [128,128]
    dim3 gN(1, (NN + 127) / 128);
    gemm_bias<128,128,16,8,8><<<gN, 256>>>(x, Wq, bq, pq, NN, HC, DINF);
    gemm_bias<128,128,16,8,8><<<gN, 256>>>(x, Wk, bk, pk, NN, HC, DINF);
    gemm_bias<128,128,16,8,8><<<gN, 256>>>(x, Wv, bv, pv, NN, HC, DINF);

    // u precompute (replaces ea2 GEMM)
    compute_u<<<(NN + GN - 1)/GN, 256, U_SMEM>>>();

    // attention: logits + max, exp + sum, CSR aggregation
    attn_logits<<<EE / 8, 256>>>(ei, ea, be2);
    attn_exp<<<(EE * HH + 255) / 256, 256>>>(ei);
    aggregate_attn<<<(NN*32 + 255)/256, 256>>>(ei, ea);

    // x_gat = [va | y | ind] @ [Wcon; Wfold; bc]  ([50000,656] @ [656,32])
    gemm_bias<128,32,16,4,4><<<dim3(1, (NN + 127)/128), 256>>>(pay, pwbig, nullptr, pxgat, NN, CC, AYW);

    // batchnorm + gelu -> out1
    bn_stats<<<256, 256>>>();
    bn_final<<<1, 32>>>();
    bn_apply<<<(NN * CC + 255) / 256, 256>>>(bn_w, bn_b, out1);

    // hypergraph branch: o1 = se@Wh1 + x@Wh2, then edge output
    aggregate_hyper<<<(NN*32 + 255)/256, 256>>>(ea);
    copy_x<<<(NN*32 + 255)/256, 256>>>(x);
    gemm_bias<128,32,16,4,4><<<dim3(1, (NN + 127)/128), 256>>>(paxh, pwh, nullptr, po1, NN, CC, 256);
    hyper_out<<<(E2 * CC + 255) / 256, 256>>>(ei, bh, out2);
}

// round 4
// speedup vs baseline: 3.2431x; 1.1738x over previous
#include <cuda_runtime.h>
#include <math.h>
#include <stdint.h>

#define NN 50000
#define EE 512000
#define E2 (EE/2)
#define DINF 128
#define HC 128
#define CC 32
#define HH 4
#define AYW 656   // 128 va | 512 y | 1 ind | 15 pad
#define NB_SCAN ((NN + 1023) / 1024)

// ---------------- scratch ----------------
__device__ float    g_q[NN*HC];
__device__ float    g_k[NN*HC];
__device__ float    g_v[NN*HC];
__device__ float    g_u[(size_t)NN*HH*DINF];   // u[n][h][f]
__device__ float    g_we2t[DINF*HC];
__device__ float    g_l1[EE*HH];               // raw logits, CSR order
__device__ float    g_l2[EE*HH];
__device__ float    g_ay[(size_t)NN*AYW];      // [va | y | ind | pad]
__device__ float    g_axh[(size_t)NN*256];     // [se_scaled | x]
__device__ float    g_wbig[AYW*CC];            // [Wcon; Wfold; bc; 0]
__device__ float    g_wh[256*CC];              // [Wh1; Wh2]
__device__ float    g_xgat[NN*CC];
__device__ float    g_o1[NN*CC];
__device__ double   g_sum[CC];
__device__ double   g_sumsq[CC];
__device__ float    g_mu[CC];
__device__ float    g_rstd[CC];
// CSR
__device__ int      g_cntA[NN];
__device__ int      g_cntH[NN];
__device__ int      g_offA[NN+1];
__device__ int      g_offH[NN+1];
__device__ int      g_curA[NN];
__device__ int      g_curH[NN];
__device__ int      g_payA[EE];
__device__ int      g_payH[EE];
__device__ int      g_blkA[NB_SCAN+1];
__device__ int      g_blkH[NB_SCAN+1];

// ---------------- zero scratch ----------------
__global__ void zero_kernel() {
    int i = blockIdx.x * blockDim.x + threadIdx.x;
    int stride = gridDim.x * blockDim.x;
    for (int j = i; j < NN; j += stride) { g_cntA[j]=0; g_cntH[j]=0; }
    if (i < CC) { g_sum[i]=0.0; g_sumsq[i]=0.0; }
}

__global__ void transpose_we2(const float* __restrict__ We2) {
    int i = blockIdx.x * blockDim.x + threadIdx.x;
    if (i < DINF*HC) {
        int f = i >> 7, o = i & 127;
        g_we2t[o*DINF + f] = We2[i];
    }
}

// ---------------- weight prep ----------------
__global__ void prep_weights(const float* __restrict__ Wcon, const float* __restrict__ We3,
                             const float* __restrict__ be3,
                             const float* __restrict__ Wh1, const float* __restrict__ Wh2) {
    int idx = blockIdx.x * blockDim.x + threadIdx.x;
    int total = AYW*CC + 256*CC;
    if (idx >= total) return;
    if (idx < AYW*CC) {
        int r = idx / CC, c = idx % CC;
        float v;
        if (r < 128) {
            v = Wcon[r*CC + c];
        } else if (r < 640) {
            int h = (r - 128) >> 7, f = (r - 128) & 127;
            float a = 0.f;
            #pragma unroll
            for (int c2 = 0; c2 < 32; c2++)
                a = fmaf(We3[f*HC + h*32 + c2], Wcon[(h*32 + c2)*CC + c], a);
            v = a;
        } else if (r == 640) {
            float a = 0.f;
            for (int k = 0; k < HC; k++)
                a = fmaf(be3[k], Wcon[k*CC + c], a);
            v = a;
        } else v = 0.f;
        g_wbig[r*CC + c] = v;
    } else {
        int j = idx - AYW*CC;
        int r = j / CC, c = j % CC;
        g_wh[r*CC + c] = (r < 128) ? Wh1[r*CC + c] : Wh2[(r-128)*CC + c];
    }
}

// ---------------- CSR build ----------------
__global__ void csr_count(const int* __restrict__ ei) {
    int i = blockIdx.x * blockDim.x + threadIdx.x;
    if (i >= EE) return;
    atomicAdd(&g_cntA[ei[EE + i]], 1);
    if (i < E2) {
        atomicAdd(&g_cntH[ei[i]],      1);
        atomicAdd(&g_cntH[ei[EE + i]], 1);
    }
}

// multi-block scan: step 1 — per-block exclusive scan + block total
__global__ void scan1(const int* __restrict__ cnt, int* __restrict__ off, int* __restrict__ blk) {
    __shared__ int sd[1024];
    int tid = threadIdx.x;
    int i = blockIdx.x * 1024 + tid;
    int v = (i < NN) ? cnt[i] : 0;
    sd[tid] = v;
    __syncthreads();
    #pragma unroll
    for (int ofs = 1; ofs < 1024; ofs <<= 1) {
        int t = (tid >= ofs) ? sd[tid - ofs] : 0;
        __syncthreads();
        sd[tid] += t;
        __syncthreads();
    }
    if (i < NN) off[i] = sd[tid] - v;
    if (tid == 1023) blk[blockIdx.x] = sd[1023];
}

// step 2 — serial scan of block totals (49 elements)
__global__ void scan2(int* __restrict__ blk) {
    if (threadIdx.x == 0) {
        int run = 0;
        for (int b = 0; b < NB_SCAN; b++) { int t = blk[b]; blk[b] = run; run += t; }
        blk[NB_SCAN] = run;
    }
}

// step 3 — add block offsets, init cursors, write tail
__global__ void scan3(int* __restrict__ off, int* __restrict__ cur, const int* __restrict__ blk) {
    int i = blockIdx.x * blockDim.x + threadIdx.x;
    if (i < NN) {
        int o = off[i] + blk[i >> 10];
        off[i] = o;
        cur[i] = o;
    }
    if (i == 0) off[NN] = blk[NB_SCAN];
}

__global__ void csr_fill(const int* __restrict__ ei) {
    int i = blockIdx.x * blockDim.x + threadIdx.x;
    if (i >= EE) return;
    int d = ei[EE + i];
    int pos = atomicAdd(&g_curA[d], 1);
    g_payA[pos] = i;
    if (i < E2) {
        int p1 = atomicAdd(&g_curH[ei[i]], 1);
        g_payH[p1] = i;
        int p2 = atomicAdd(&g_curH[ei[EE + i]], 1);
        g_payH[p2] = i;
    }
}

// ---------------- double-buffered register-tiled SGEMM ----------------
template<int BM, int BN, int BK, int TM, int TN>
__global__ void __launch_bounds__((BM/TM)*(BN/TN), 2)
gemm_bias(const float* __restrict__ A, const float* __restrict__ W,
          const float* __restrict__ bias, float* __restrict__ C,
          int M, int N, int K) {
    constexpr int THREADS = (BM/TM)*(BN/TN);
    constexpr int A4 = BM*BK/4;
    constexpr int W4 = BK*BN/4;
    constexpr int AI = (A4 + THREADS - 1)/THREADS;
    constexpr int WI = (W4 + THREADS - 1)/THREADS;
    __shared__ float As[2][BK][BM+4];
    __shared__ float Ws[2][BK][BN];
    const int tid  = threadIdx.x;
    const int brow = blockIdx.y * BM;
    const int bcol = blockIdx.x * BN;
    const int trow = (tid / (BN/TN)) * TM;
    const int tcol = (tid % (BN/TN)) * TN;

    float4 stA[AI];
    float4 stW[WI];

    auto loadg = [&](int k0) {
        #pragma unroll
        for (int it = 0; it < AI; it++) {
            int i = tid + it*THREADS;
            if (i < A4) {
                int m = i / (BK/4), k4 = i % (BK/4);
                int gm = brow + m;
                stA[it] = (gm < M) ? *(const float4*)(A + (size_t)gm*K + k0 + k4*4)
                                   : make_float4(0.f,0.f,0.f,0.f);
            }
        }
        #pragma unroll
        for (int it = 0; it < WI; it++) {
            int i = tid + it*THREADS;
            if (i < W4) {
                int kk = i / (BN/4), n4 = i % (BN/4);
                stW[it] = *(const float4*)(W + (size_t)(k0+kk)*N + bcol + n4*4);
            }
        }
    };
    auto store_s = [&](int buf) {
        #pragma unroll
        for (int it = 0; it < AI; it++) {
            int i = tid + it*THREADS;
            if (i < A4) {
                int m = i / (BK/4), k4 = i % (BK/4);
                As[buf][k4*4+0][m] = stA[it].x;
                As[buf][k4*4+1][m] = stA[it].y;
                As[buf][k4*4+2][m] = stA[it].z;
                As[buf][k4*4+3][m] = stA[it].w;
            }
        }
        #pragma unroll
        for (int it = 0; it < WI; it++) {
            int i = tid + it*THREADS;
            if (i < W4) {
                int kk = i / (BN/4), n4 = i % (BN/4);
                *(float4*)&Ws[buf][kk][n4*4] = stW[it];
            }
        }
    };

    float acc[TM][TN];
    #pragma unroll
    for (int i = 0; i < TM; i++)
        #pragma unroll
        for (int j = 0; j < TN; j++) acc[i][j] = 0.f;

    const int nt = K / BK;
    loadg(0);
    store_s(0);
    __syncthreads();

    for (int t = 0; t < nt; t++) {
        int cur = t & 1;
        if (t + 1 < nt) loadg((t+1)*BK);
        #pragma unroll
        for (int kk = 0; kk < BK; kk++) {
            float ra[TM], rb[TN];
            #pragma unroll
            for (int i = 0; i < TM; i += 4)
                *(float4*)&ra[i] = *(const float4*)&As[cur][kk][trow + i];
            #pragma unroll
            for (int j = 0; j < TN; j += 4)
                *(float4*)&rb[j] = *(const float4*)&Ws[cur][kk][tcol + j];
            #pragma unroll
            for (int i = 0; i < TM; i++)
                #pragma unroll
                for (int j = 0; j < TN; j++)
                    acc[i][j] = fmaf(ra[i], rb[j], acc[i][j]);
        }
        if (t + 1 < nt) {
            store_s((t+1) & 1);
            __syncthreads();
        }
    }

    #pragma unroll
    for (int i = 0; i < TM; i++) {
        int gm = brow + trow + i;
        if (gm >= M) continue;
        #pragma unroll
        for (int j = 0; j < TN; j += 4) {
            int gn = bcol + tcol + j;
            float4 v;
            v.x = acc[i][j+0] + (bias ? bias[gn+0] : 0.f);
            v.y = acc[i][j+1] + (bias ? bias[gn+1] : 0.f);
            v.z = acc[i][j+2] + (bias ? bias[gn+2] : 0.f);
            v.w = acc[i][j+3] + (bias ? bias[gn+3] : 0.f);
            *(float4*)(C + (size_t)gm*N + gn) = v;
        }
    }
}

// ---------------- u precompute ----------------
#define GN 32
__global__ void compute_u() {
    extern __shared__ float shm[];
    float (*sW)[132] = (float (*)[132])shm;
    float (*sq)[128] = (float (*)[128])(shm + 128*132);
    int tid = threadIdx.x;
    int n0 = blockIdx.x * GN;
    for (int i = tid; i < 128*128; i += 256) {
        int o = i >> 7, f = i & 127;
        sW[o][f] = g_we2t[i];
    }
    for (int i = tid; i < GN*128; i += 256) {
        int nl = i >> 7, c = i & 127;
        int n = n0 + nl;
        sq[nl][c] = (n < NN) ? g_q[(size_t)n*128 + c] : 0.f;
    }
    __syncthreads();
    int w = tid >> 5, lane = tid & 31;
    for (int p = w; p < GN*HH; p += 8) {
        int nl = p >> 2, h = p & 3;
        int n = n0 + nl;
        if (n >= NN) continue;
        float a0=0.f, a1=0.f, a2=0.f, a3=0.f;
        #pragma unroll
        for (int c = 0; c < 32; c++) {
            float qv = sq[nl][h*32 + c];
            const float* row = sW[h*32 + c];
            a0 = fmaf(qv, row[lane],      a0);
            a1 = fmaf(qv, row[lane + 32], a1);
            a2 = fmaf(qv, row[lane + 64], a2);
            a3 = fmaf(qv, row[lane + 96], a3);
        }
        size_t base = (size_t)n*512 + h*128;
        g_u[base + lane]      = a0;
        g_u[base + lane + 32] = a1;
        g_u[base + lane + 64] = a2;
        g_u[base + lane + 96] = a3;
    }
}

// ---------------- fused attention: warp per dst node, no atomics ----------------
__global__ void attn_fused(const int* __restrict__ ei, const float* __restrict__ ea,
                           const float* __restrict__ be2) {
    int w = (blockIdx.x * blockDim.x + threadIdx.x) >> 5;
    if (w >= NN) return;
    int lane = threadIdx.x & 31;
    const int d = w;
    const int beg = g_offA[d], end = g_offA[d+1];
    const float scale = 0.17677669529663687f;

    // per-node operands (loaded once)
    float qv[HH], b2[HH], uu[HH][4];
    #pragma unroll
    for (int h = 0; h < HH; h++) {
        qv[h] = g_q[(size_t)d*HC + h*32 + lane];
        b2[h] = be2[h*32 + lane];
        #pragma unroll
        for (int j = 0; j < 4; j++)
            uu[h][j] = g_u[(size_t)d*512 + h*128 + j*32 + lane];
    }

    // ---- phase A: logits + max ----
    float m1[HH], m2[HH];
    #pragma unroll
    for (int h = 0; h < HH; h++) { m1[h] = -INFINITY; m2[h] = -INFINITY; }

    for (int idx = beg; idx < end; idx++) {
        int e = g_payA[idx];
        int s = ei[e];
        float r[4];
        #pragma unroll
        for (int j = 0; j < 4; j++) r[j] = ea[(size_t)e*128 + j*32 + lane];
        float l1v[HH], l2v[HH];
        #pragma unroll
        for (int h = 0; h < HH; h++) {
            float kv = g_k[(size_t)s*HC + h*32 + lane];
            float p1 = qv[h] * kv;
            float p2 = qv[h] * b2[h];
            #pragma unroll
            for (int j = 0; j < 4; j++) p2 = fmaf(r[j], uu[h][j], p2);
            #pragma unroll
            for (int o = 16; o > 0; o >>= 1) {
                p1 += __shfl_xor_sync(0xffffffffu, p1, o);
                p2 += __shfl_xor_sync(0xffffffffu, p2, o);
            }
            l1v[h] = p1 * scale;
            l2v[h] = p2 * scale;
            m1[h] = fmaxf(m1[h], l1v[h]);
            m2[h] = fmaxf(m2[h], l2v[h]);
        }
        // lanes 0-3 store l1[h=lane], lanes 4-7 store l2[h=lane-4] (values uniform across warp)
        if (lane < 8) {
            int h = lane & 3;
            float val = (lane < 4)
                ? ((h==0)?l1v[0]:(h==1)?l1v[1]:(h==2)?l1v[2]:l1v[3])
                : ((h==0)?l2v[0]:(h==1)?l2v[1]:(h==2)?l2v[2]:l2v[3]);
            if (lane < 4) g_l1[idx*4 + h] = val;
            else          g_l2[idx*4 + h] = val;
        }
    }

    // ---- phase B: exp + sums + weighted aggregation ----
    int hsel = lane >> 3;   // head owning channels [lane*4, lane*4+4)
    float4 va = make_float4(0.f,0.f,0.f,0.f);
    float4 y0 = va, y1 = va, y2 = va, y3 = va;
    float s1[HH] = {0.f,0.f,0.f,0.f};
    float s2[HH] = {0.f,0.f,0.f,0.f};

    for (int idx = beg; idx < end; idx++) {
        int e = g_payA[idx];
        int s = ei[e];
        float4 L1 = *(const float4*)&g_l1[idx*4];   // broadcast load
        float4 L2 = *(const float4*)&g_l2[idx*4];
        float ex1[HH], ex2[HH];
        ex1[0] = __expf(L1.x - m1[0]); ex1[1] = __expf(L1.y - m1[1]);
        ex1[2] = __expf(L1.z - m1[2]); ex1[3] = __expf(L1.w - m1[3]);
        ex2[0] = __expf(L2.x - m2[0]); ex2[1] = __expf(L2.y - m2[1]);
        ex2[2] = __expf(L2.z - m2[2]); ex2[3] = __expf(L2.w - m2[3]);
        #pragma unroll
        for (int h = 0; h < HH; h++) { s1[h] += ex1[h]; s2[h] += ex2[h]; }

        float4 eav = *(const float4*)&ea[(size_t)e*128 + lane*4];
        float4 vv  = *(const float4*)&g_v[(size_t)s*128 + lane*4];
        y0.x = fmaf(ex2[0], eav.x, y0.x); y0.y = fmaf(ex2[0], eav.y, y0.y);
        y0.z = fmaf(ex2[0], eav.z, y0.z); y0.w = fmaf(ex2[0], eav.w, y0.w);
        y1.x = fmaf(ex2[1], eav.x, y1.x); y1.y = fmaf(ex2[1], eav.y, y1.y);
        y1.z = fmaf(ex2[1], eav.z, y1.z); y1.w = fmaf(ex2[1], eav.w, y1.w);
        y2.x = fmaf(ex2[2], eav.x, y2.x); y2.y = fmaf(ex2[2], eav.y, y2.y);
        y2.z = fmaf(ex2[2], eav.z, y2.z); y2.w = fmaf(ex2[2], eav.w, y2.w);
        y3.x = fmaf(ex2[3], eav.x, y3.x); y3.y = fmaf(ex2[3], eav.y, y3.y);
        y3.z = fmaf(ex2[3], eav.z, y3.z); y3.w = fmaf(ex2[3], eav.w, y3.w);
        float e1 = ex1[0];
        if (hsel == 1) e1 = ex1[1]; else if (hsel == 2) e1 = ex1[2]; else if (hsel == 3) e1 = ex1[3];
        va.x = fmaf(e1, vv.x, va.x); va.y = fmaf(e1, vv.y, va.y);
        va.z = fmaf(e1, vv.z, va.z); va.w = fmaf(e1, vv.w, va.w);
    }

    float r1 = 1.f / (s1[hsel] + 1e-16f);
    va.x *= r1; va.y *= r1; va.z *= r1; va.w *= r1;
    float q0 = 1.f/(s2[0]+1e-16f), q1 = 1.f/(s2[1]+1e-16f);
    float q2 = 1.f/(s2[2]+1e-16f), q3 = 1.f/(s2[3]+1e-16f);
    y0.x*=q0; y0.y*=q0; y0.z*=q0; y0.w*=q0;
    y1.x*=q1; y1.y*=q1; y1.z*=q1; y1.w*=q1;
    y2.x*=q2; y2.y*=q2; y2.z*=q2; y2.w*=q2;
    y3.x*=q3; y3.y*=q3; y3.z*=q3; y3.w*=q3;

    float* row = g_ay + (size_t)d*AYW;
    *(float4*)&row[lane*4]               = va;
    *(float4*)&row[128 + 0*128 + lane*4] = y0;
    *(float4*)&row[128 + 1*128 + lane*4] = y1;
    *(float4*)&row[128 + 2*128 + lane*4] = y2;
    *(float4*)&row[128 + 3*128 + lane*4] = y3;
    if (lane == 0)      row[640] = (end > beg) ? 1.f : 0.f;
    else if (lane < 16) row[640 + lane] = 0.f;
}

// ---------------- hyper aggregation (warp per node, CSR) ----------------
__global__ void aggregate_hyper(const float* __restrict__ ea) {
    int w = (blockIdx.x * blockDim.x + threadIdx.x) >> 5;
    if (w >= NN) return;
    int lane = threadIdx.x & 31;
    int beg = g_offH[w], end = g_offH[w+1];
    float4 acc = make_float4(0.f,0.f,0.f,0.f);
    for (int idx = beg; idx < end; idx++) {
        int i = g_payH[idx];
        float4 eav = *(const float4*)&ea[(size_t)i*128 + lane*4];
        acc.x += eav.x; acc.y += eav.y; acc.z += eav.z; acc.w += eav.w;
    }
    int len = end - beg;
    float binv = (len > 0) ? (1.f / (float)len) : 0.f;
    acc.x *= binv; acc.y *= binv; acc.z *= binv; acc.w *= binv;
    *(float4*)&g_axh[(size_t)w*256 + lane*4] = acc;
}

__global__ void copy_x(const float* __restrict__ x) {
    int idx = blockIdx.x * blockDim.x + threadIdx.x;
    if (idx >= NN*32) return;
    int n = idx >> 5, c4 = idx & 31;
    *(float4*)&g_axh[(size_t)n*256 + 128 + c4*4] = *(const float4*)&x[(size_t)n*128 + c4*4];
}

// ---------------- BatchNorm ----------------
__global__ void bn_stats() {
    __shared__ float ssum[8][CC], ssq[8][CC];
    int c  = threadIdx.x & 31;
    int ry = threadIdx.x >> 5;
    float s = 0.f, q = 0.f;
    for (int r = blockIdx.x * 8 + ry; r < NN; r += gridDim.x * 8) {
        float v = g_xgat[r*CC + c];
        s += v; q += v * v;
    }
    ssum[ry][c] = s; ssq[ry][c] = q;
    __syncthreads();
    if (ry == 0) {
        #pragma unroll
        for (int i = 1; i < 8; i++) { s += ssum[i][c]; q += ssq[i][c]; }
        atomicAdd(&g_sum[c],   (double)s);
        atomicAdd(&g_sumsq[c], (double)q);
    }
}

__global__ void bn_final() {
    int c = threadIdx.x;
    if (c < CC) {
        double mu  = g_sum[c] / (double)NN;
        double var = g_sumsq[c] / (double)NN - mu * mu;
        g_mu[c]   = (float)mu;
        g_rstd[c] = (float)(1.0 / sqrt(var + 1e-5));
    }
}

__global__ void bn_apply(const float* __restrict__ bn_w, const float* __restrict__ bn_b,
                         float* __restrict__ out1) {
    int i = blockIdx.x * blockDim.x + threadIdx.x;
    if (i >= NN*CC) return;
    int c = i & 31;
    float xn = bn_w[c] * (g_xgat[i] - g_mu[c]) * g_rstd[c] + bn_b[c];
    out1[i] = 0.5f * xn * (1.0f + erff(xn * 0.70710678118654752f));
}

// ---------------- hyper output ----------------
__global__ void hyper_out(const int* __restrict__ ei, const float* __restrict__ bh,
                          float* __restrict__ out2) {
    int idx = blockIdx.x * blockDim.x + threadIdx.x;
    if (idx >= E2*CC) return;
    int i = idx >> 5, c = idx & 31;
    out2[idx] = 0.5f * (g_o1[ei[i]*CC + c] + g_o1[ei[EE + i]*CC + c]) + bh[c];
}

// ---------------- launcher ----------------
extern "C" void kernel_launch(void* const* d_in, const int* in_sizes, int n_in,
                              void* d_out, int out_size) {
    const float* x    = (const float*)d_in[0];
    const float* ea   = (const float*)d_in[1];
    const float* Wq   = (const float*)d_in[2];
    const float* bq   = (const float*)d_in[3];
    const float* Wk   = (const float*)d_in[4];
    const float* bk   = (const float*)d_in[5];
    const float* Wv   = (const float*)d_in[6];
    const float* bv   = (const float*)d_in[7];
    const float* We2  = (const float*)d_in[8];
    const float* be2  = (const float*)d_in[9];
    const float* We3  = (const float*)d_in[10];
    const float* be3  = (const float*)d_in[11];
    const float* Wcon = (const float*)d_in[12];
    const float* bn_w = (const float*)d_in[13];
    const float* bn_b = (const float*)d_in[14];
    const float* Wh1  = (const float*)d_in[15];
    const float* Wh2  = (const float*)d_in[16];
    const float* bh   = (const float*)d_in[17];
    const int*   ei   = (const int*)d_in[18];

    float* out  = (float*)d_out;
    float* out1 = out;
    float* out2 = out + (size_t)NN * CC;

    float *pq, *pk, *pv, *pay, *paxh, *pwbig, *pwh, *pxgat, *po1;
    int *pcntA, *pcntH, *poffA, *poffH, *pcurA, *pcurH, *pblkA, *pblkH;
    cudaGetSymbolAddress((void**)&pq,    g_q);
    cudaGetSymbolAddress((void**)&pk,    g_k);
    cudaGetSymbolAddress((void**)&pv,    g_v);
    cudaGetSymbolAddress((void**)&pay,   g_ay);
    cudaGetSymbolAddress((void**)&paxh,  g_axh);
    cudaGetSymbolAddress((void**)&pwbig, g_wbig);
    cudaGetSymbolAddress((void**)&pwh,   g_wh);
    cudaGetSymbolAddress((void**)&pxgat, g_xgat);
    cudaGetSymbolAddress((void**)&po1,   g_o1);
    cudaGetSymbolAddress((void**)&pcntA, g_cntA);
    cudaGetSymbolAddress((void**)&pcntH, g_cntH);
    cudaGetSymbolAddress((void**)&poffA, g_offA);
    cudaGetSymbolAddress((void**)&poffH, g_offH);
    cudaGetSymbolAddress((void**)&pcurA, g_curA);
    cudaGetSymbolAddress((void**)&pcurH, g_curH);
    cudaGetSymbolAddress((void**)&pblkA, g_blkA);
    cudaGetSymbolAddress((void**)&pblkH, g_blkH);

    const int U_SMEM = (128*132 + GN*128) * 4;
    cudaFuncSetAttribute(compute_u, cudaFuncAttributeMaxDynamicSharedMemorySize, U_SMEM);

    zero_kernel<<<256, 256>>>();
    transpose_we2<<<64, 256>>>(We2);
    prep_weights<<<(AYW*CC + 256*CC + 255)/256, 256>>>(Wcon, We3, be3, Wh1, Wh2);

    // CSR build (parallel scans)
    csr_count<<<(EE + 255)/256, 256>>>(ei);
    scan1<<<NB_SCAN, 1024>>>(pcntA, poffA, pblkA);
    scan1<<<NB_SCAN, 1024>>>(pcntH, poffH, pblkH);
    scan2<<<1, 32>>>(pblkA);
    scan2<<<1, 32>>>(pblkH);
    scan3<<<(NN + 255)/256, 256>>>(poffA, pcurA, pblkA);
    scan3<<<(NN + 255)/256, 256>>>(poffH, pcurH, pblkH);
    csr_fill<<<(EE + 255)/256, 256>>>(ei);

    // node projections
    dim3 gN(1, (NN + 127) / 128);
    gemm_bias<128,128,16,8,8><<<gN, 256>>>(x, Wq, bq, pq, NN, HC, DINF);
    gemm_bias<128,128,16,8,8><<<gN, 256>>>(x, Wk, bk, pk, NN, HC, DINF);
    gemm_bias<128,128,16,8,8><<<gN, 256>>>(x, Wv, bv, pv, NN, HC, DINF);

    // u precompute
    compute_u<<<(NN + GN - 1)/GN, 256, U_SMEM>>>();

    // fused attention (no atomics)
    attn_fused<<<(NN*32 + 255)/256, 256>>>(ei, ea, be2);

    // x_gat = [va | y | ind] @ Wbig
    gemm_bias<128,32,16,4,4><<<dim3(1, (NN + 127)/128), 256>>>(pay, pwbig, nullptr, pxgat, NN, CC, AYW);

    // batchnorm + gelu -> out1
    bn_stats<<<256, 256>>>();
    bn_final<<<1, 32>>>();
    bn_apply<<<(NN * CC + 255) / 256, 256>>>(bn_w, bn_b, out1);

    // hypergraph branch
    aggregate_hyper<<<(NN*32 + 255)/256, 256>>>(ea);
    copy_x<<<(NN*32 + 255)/256, 256>>>(x);
    gemm_bias<128,32,16,4,4><<<dim3(1, (NN + 127)/128), 256>>>(paxh, pwh, nullptr, po1, NN, CC, 256);
    hyper_out<<<(E2 * CC + 255) / 256, 256>>>(ei, bh, out2);
}

// round 5
// speedup vs baseline: 3.2476x; 1.0014x over previous
#include <cuda_runtime.h>
#include <math.h>
#include <stdint.h>

#define NN 50000
#define EE 512000
#define E2 (EE/2)
#define DINF 128
#define HC 128
#define CC 32
#define HH 4
#define AYW 656   // 128 va | 512 y | 1 ind | 15 pad
#define NB_SCAN ((NN + 1023) / 1024)

// ---------------- scratch ----------------
__device__ float    g_q[NN*HC];
__device__ float    g_k[NN*HC];
__device__ float    g_v[NN*HC];
__device__ float    g_u[(size_t)NN*HH*DINF];   // u[n][h][f]
__device__ float    g_we2t[DINF*HC];
__device__ float    g_ay[(size_t)NN*AYW];      // [va | y | ind | pad]
__device__ float    g_axh[(size_t)NN*256];     // [se_scaled | x]
__device__ float    g_wbig[AYW*CC];            // [Wcon; Wfold; bc; 0]
__device__ float    g_wh[256*CC];              // [Wh1; Wh2]
__device__ float    g_xgat[NN*CC];
__device__ float    g_o1[NN*CC];
__device__ double   g_sum[CC];
__device__ double   g_sumsq[CC];
__device__ float    g_mu[CC];
__device__ float    g_rstd[CC];
// CSR
__device__ int      g_cntA[NN];
__device__ int      g_cntH[NN];
__device__ int      g_offA[NN+1];
__device__ int      g_offH[NN+1];
__device__ int      g_curA[NN];
__device__ int      g_curH[NN];
__device__ int      g_payA[EE];
__device__ int      g_payH[EE];
__device__ int      g_blkA[NB_SCAN+1];
__device__ int      g_blkH[NB_SCAN+1];

// ---------------- zero scratch ----------------
__global__ void zero_kernel() {
    int i = blockIdx.x * blockDim.x + threadIdx.x;
    int stride = gridDim.x * blockDim.x;
    for (int j = i; j < NN; j += stride) { g_cntA[j]=0; g_cntH[j]=0; }
    if (i < CC) { g_sum[i]=0.0; g_sumsq[i]=0.0; }
}

__global__ void transpose_we2(const float* __restrict__ We2) {
    int i = blockIdx.x * blockDim.x + threadIdx.x;
    if (i < DINF*HC) {
        int f = i >> 7, o = i & 127;
        g_we2t[o*DINF + f] = We2[i];
    }
}

// ---------------- weight prep ----------------
__global__ void prep_weights(const float* __restrict__ Wcon, const float* __restrict__ We3,
                             const float* __restrict__ be3,
                             const float* __restrict__ Wh1, const float* __restrict__ Wh2) {
    int idx = blockIdx.x * blockDim.x + threadIdx.x;
    int total = AYW*CC + 256*CC;
    if (idx >= total) return;
    if (idx < AYW*CC) {
        int r = idx / CC, c = idx % CC;
        float v;
        if (r < 128) {
            v = Wcon[r*CC + c];
        } else if (r < 640) {
            int h = (r - 128) >> 7, f = (r - 128) & 127;
            float a = 0.f;
            #pragma unroll
            for (int c2 = 0; c2 < 32; c2++)
                a = fmaf(We3[f*HC + h*32 + c2], Wcon[(h*32 + c2)*CC + c], a);
            v = a;
        } else if (r == 640) {
            float a = 0.f;
            for (int k = 0; k < HC; k++)
                a = fmaf(be3[k], Wcon[k*CC + c], a);
            v = a;
        } else v = 0.f;
        g_wbig[r*CC + c] = v;
    } else {
        int j = idx - AYW*CC;
        int r = j / CC, c = j % CC;
        g_wh[r*CC + c] = (r < 128) ? Wh1[r*CC + c] : Wh2[(r-128)*CC + c];
    }
}

// ---------------- CSR build ----------------
__global__ void csr_count(const int* __restrict__ ei) {
    int i = blockIdx.x * blockDim.x + threadIdx.x;
    if (i >= EE) return;
    atomicAdd(&g_cntA[ei[EE + i]], 1);
    if (i < E2) {
        atomicAdd(&g_cntH[ei[i]],      1);
        atomicAdd(&g_cntH[ei[EE + i]], 1);
    }
}

__global__ void scan1(const int* __restrict__ cnt, int* __restrict__ off, int* __restrict__ blk) {
    __shared__ int sd[1024];
    int tid = threadIdx.x;
    int i = blockIdx.x * 1024 + tid;
    int v = (i < NN) ? cnt[i] : 0;
    sd[tid] = v;
    __syncthreads();
    #pragma unroll
    for (int ofs = 1; ofs < 1024; ofs <<= 1) {
        int t = (tid >= ofs) ? sd[tid - ofs] : 0;
        __syncthreads();
        sd[tid] += t;
        __syncthreads();
    }
    if (i < NN) off[i] = sd[tid] - v;
    if (tid == 1023) blk[blockIdx.x] = sd[1023];
}

__global__ void scan2(int* __restrict__ blk) {
    if (threadIdx.x == 0) {
        int run = 0;
        for (int b = 0; b < NB_SCAN; b++) { int t = blk[b]; blk[b] = run; run += t; }
        blk[NB_SCAN] = run;
    }
}

__global__ void scan3(int* __restrict__ off, int* __restrict__ cur, const int* __restrict__ blk) {
    int i = blockIdx.x * blockDim.x + threadIdx.x;
    if (i < NN) {
        int o = off[i] + blk[i >> 10];
        off[i] = o;
        cur[i] = o;
    }
    if (i == 0) off[NN] = blk[NB_SCAN];
}

__global__ void csr_fill(const int* __restrict__ ei) {
    int i = blockIdx.x * blockDim.x + threadIdx.x;
    if (i >= EE) return;
    int d = ei[EE + i];
    int pos = atomicAdd(&g_curA[d], 1);
    g_payA[pos] = i;
    if (i < E2) {
        int p1 = atomicAdd(&g_curH[ei[i]], 1);
        g_payH[p1] = i;
        int p2 = atomicAdd(&g_curH[ei[EE + i]], 1);
        g_payH[p2] = i;
    }
}

// ---------------- double-buffered register-tiled SGEMM ----------------
template<int BM, int BN, int BK, int TM, int TN>
__global__ void __launch_bounds__((BM/TM)*(BN/TN), 2)
gemm_bias(const float* __restrict__ A, const float* __restrict__ W,
          const float* __restrict__ bias, float* __restrict__ C,
          int M, int N, int K) {
    constexpr int THREADS = (BM/TM)*(BN/TN);
    constexpr int A4 = BM*BK/4;
    constexpr int W4 = BK*BN/4;
    constexpr int AI = (A4 + THREADS - 1)/THREADS;
    constexpr int WI = (W4 + THREADS - 1)/THREADS;
    __shared__ float As[2][BK][BM+4];
    __shared__ float Ws[2][BK][BN];
    const int tid  = threadIdx.x;
    const int brow = blockIdx.y * BM;
    const int bcol = blockIdx.x * BN;
    const int trow = (tid / (BN/TN)) * TM;
    const int tcol = (tid % (BN/TN)) * TN;

    float4 stA[AI];
    float4 stW[WI];

    auto loadg = [&](int k0) {
        #pragma unroll
        for (int it = 0; it < AI; it++) {
            int i = tid + it*THREADS;
            if (i < A4) {
                int m = i / (BK/4), k4 = i % (BK/4);
                int gm = brow + m;
                stA[it] = (gm < M) ? *(const float4*)(A + (size_t)gm*K + k0 + k4*4)
                                   : make_float4(0.f,0.f,0.f,0.f);
            }
        }
        #pragma unroll
        for (int it = 0; it < WI; it++) {
            int i = tid + it*THREADS;
            if (i < W4) {
                int kk = i / (BN/4), n4 = i % (BN/4);
                stW[it] = *(const float4*)(W + (size_t)(k0+kk)*N + bcol + n4*4);
            }
        }
    };
    auto store_s = [&](int buf) {
        #pragma unroll
        for (int it = 0; it < AI; it++) {
            int i = tid + it*THREADS;
            if (i < A4) {
                int m = i / (BK/4), k4 = i % (BK/4);
                As[buf][k4*4+0][m] = stA[it].x;
                As[buf][k4*4+1][m] = stA[it].y;
                As[buf][k4*4+2][m] = stA[it].z;
                As[buf][k4*4+3][m] = stA[it].w;
            }
        }
        #pragma unroll
        for (int it = 0; it < WI; it++) {
            int i = tid + it*THREADS;
            if (i < W4) {
                int kk = i / (BN/4), n4 = i % (BN/4);
                *(float4*)&Ws[buf][kk][n4*4] = stW[it];
            }
        }
    };

    float acc[TM][TN];
    #pragma unroll
    for (int i = 0; i < TM; i++)
        #pragma unroll
        for (int j = 0; j < TN; j++) acc[i][j] = 0.f;

    const int nt = K / BK;
    loadg(0);
    store_s(0);
    __syncthreads();

    for (int t = 0; t < nt; t++) {
        int cur = t & 1;
        if (t + 1 < nt) loadg((t+1)*BK);
        #pragma unroll
        for (int kk = 0; kk < BK; kk++) {
            float ra[TM], rb[TN];
            #pragma unroll
            for (int i = 0; i < TM; i += 4)
                *(float4*)&ra[i] = *(const float4*)&As[cur][kk][trow + i];
            #pragma unroll
            for (int j = 0; j < TN; j += 4)
                *(float4*)&rb[j] = *(const float4*)&Ws[cur][kk][tcol + j];
            #pragma unroll
            for (int i = 0; i < TM; i++)
                #pragma unroll
                for (int j = 0; j < TN; j++)
                    acc[i][j] = fmaf(ra[i], rb[j], acc[i][j]);
        }
        if (t + 1 < nt) {
            store_s((t+1) & 1);
            __syncthreads();
        }
    }

    #pragma unroll
    for (int i = 0; i < TM; i++) {
        int gm = brow + trow + i;
        if (gm >= M) continue;
        #pragma unroll
        for (int j = 0; j < TN; j += 4) {
            int gn = bcol + tcol + j;
            float4 v;
            v.x = acc[i][j+0] + (bias ? bias[gn+0] : 0.f);
            v.y = acc[i][j+1] + (bias ? bias[gn+1] : 0.f);
            v.z = acc[i][j+2] + (bias ? bias[gn+2] : 0.f);
            v.w = acc[i][j+3] + (bias ? bias[gn+3] : 0.f);
            *(float4*)(C + (size_t)gm*N + gn) = v;
        }
    }
}

// ---------------- u precompute ----------------
#define GN 32
__global__ void compute_u() {
    extern __shared__ float shm[];
    float (*sW)[132] = (float (*)[132])shm;
    float (*sq)[128] = (float (*)[128])(shm + 128*132);
    int tid = threadIdx.x;
    int n0 = blockIdx.x * GN;
    for (int i = tid; i < 128*128; i += 256) {
        int o = i >> 7, f = i & 127;
        sW[o][f] = g_we2t[i];
    }
    for (int i = tid; i < GN*128; i += 256) {
        int nl = i >> 7, c = i & 127;
        int n = n0 + nl;
        sq[nl][c] = (n < NN) ? g_q[(size_t)n*128 + c] : 0.f;
    }
    __syncthreads();
    int w = tid >> 5, lane = tid & 31;
    for (int p = w; p < GN*HH; p += 8) {
        int nl = p >> 2, h = p & 3;
        int n = n0 + nl;
        if (n >= NN) continue;
        float a0=0.f, a1=0.f, a2=0.f, a3=0.f;
        #pragma unroll
        for (int c = 0; c < 32; c++) {
            float qv = sq[nl][h*32 + c];
            const float* row = sW[h*32 + c];
            a0 = fmaf(qv, row[lane],      a0);
            a1 = fmaf(qv, row[lane + 32], a1);
            a2 = fmaf(qv, row[lane + 64], a2);
            a3 = fmaf(qv, row[lane + 96], a3);
        }
        size_t base = (size_t)n*512 + h*128;
        g_u[base + lane]      = a0;
        g_u[base + lane + 32] = a1;
        g_u[base + lane + 64] = a2;
        g_u[base + lane + 96] = a3;
    }
}

// ---------------- fused single-pass attention: warp per dst node ----------------
// lane l: head g = l>>3, sub-slot = l&7 (4 channels of head g, 16 features of ea dot)
__global__ void attn_fused(const int* __restrict__ ei, const float* __restrict__ ea,
                           const float* __restrict__ be2) {
    int w = (blockIdx.x * blockDim.x + threadIdx.x) >> 5;
    if (w >= NN) return;
    const int lane = threadIdx.x & 31;
    const int g = lane >> 3, sub = lane & 7;
    const int d = w;
    const int beg = g_offA[d], end = g_offA[d+1];
    const float scale = 0.17677669529663687f;

    // per-node operands
    float4 qv = *(const float4*)&g_q[(size_t)d*HC + g*32 + sub*4];
    float4 b2 = *(const float4*)&be2[g*32 + sub*4];
    float qb2 = qv.x*b2.x + qv.y*b2.y + qv.z*b2.z + qv.w*b2.w;
    float4 u4[4];
    #pragma unroll
    for (int j = 0; j < 4; j++)
        u4[j] = *(const float4*)&g_u[(size_t)d*512 + g*128 + sub*16 + j*4];

    float4 va = make_float4(0.f,0.f,0.f,0.f);
    float4 y0 = va, y1 = va, y2 = va, y3 = va;
    float s1 = 0.f, s20 = 0.f, s21 = 0.f, s22 = 0.f, s23 = 0.f;

    for (int idx = beg; idx < end; idx++) {
        int e = g_payA[idx];
        int s = ei[e];
        const float* eb = ea + (size_t)e*128;

        float4 ka = *(const float4*)&g_k[(size_t)s*HC + g*32 + sub*4];
        float p1 = qv.x*ka.x + qv.y*ka.y + qv.z*ka.z + qv.w*ka.w;
        float p2 = qb2;
        #pragma unroll
        for (int j = 0; j < 4; j++) {
            float4 ev = *(const float4*)&eb[sub*16 + j*4];
            p2 += ev.x*u4[j].x + ev.y*u4[j].y + ev.z*u4[j].z + ev.w*u4[j].w;
        }
        // reduce within 8-lane head group
        #pragma unroll
        for (int o = 1; o < 8; o <<= 1) {
            p1 += __shfl_xor_sync(0xffffffffu, p1, o);
            p2 += __shfl_xor_sync(0xffffffffu, p2, o);
        }
        float ex1 = __expf(p1 * scale);   // own head's exp (uniform within group)
        float ex2 = __expf(p2 * scale);
        s1 += ex1;
        float e20 = __shfl_sync(0xffffffffu, ex2, 0);
        float e21 = __shfl_sync(0xffffffffu, ex2, 8);
        float e22 = __shfl_sync(0xffffffffu, ex2, 16);
        float e23 = __shfl_sync(0xffffffffu, ex2, 24);
        s20 += e20; s21 += e21; s22 += e22; s23 += e23;

        float4 eay = *(const float4*)&eb[lane*4];   // L1 hit (row already touched)
        float4 vv  = *(const float4*)&g_v[(size_t)s*HC + lane*4];
        va.x = fmaf(ex1, vv.x, va.x); va.y = fmaf(ex1, vv.y, va.y);
        va.z = fmaf(ex1, vv.z, va.z); va.w = fmaf(ex1, vv.w, va.w);
        y0.x = fmaf(e20, eay.x, y0.x); y0.y = fmaf(e20, eay.y, y0.y);
        y0.z = fmaf(e20, eay.z, y0.z); y0.w = fmaf(e20, eay.w, y0.w);
        y1.x = fmaf(e21, eay.x, y1.x); y1.y = fmaf(e21, eay.y, y1.y);
        y1.z = fmaf(e21, eay.z, y1.z); y1.w = fmaf(e21, eay.w, y1.w);
        y2.x = fmaf(e22, eay.x, y2.x); y2.y = fmaf(e22, eay.y, y2.y);
        y2.z = fmaf(e22, eay.z, y2.z); y2.w = fmaf(e22, eay.w, y2.w);
        y3.x = fmaf(e23, eay.x, y3.x); y3.y = fmaf(e23, eay.y, y3.y);
        y3.z = fmaf(e23, eay.z, y3.z); y3.w = fmaf(e23, eay.w, y3.w);
    }

    float r1 = 1.f / (s1 + 1e-16f);
    va.x *= r1; va.y *= r1; va.z *= r1; va.w *= r1;
    float q0 = 1.f/(s20+1e-16f), q1 = 1.f/(s21+1e-16f);
    float q2 = 1.f/(s22+1e-16f), q3 = 1.f/(s23+1e-16f);
    y0.x*=q0; y0.y*=q0; y0.z*=q0; y0.w*=q0;
    y1.x*=q1; y1.y*=q1; y1.z*=q1; y1.w*=q1;
    y2.x*=q2; y2.y*=q2; y2.z*=q2; y2.w*=q2;
    y3.x*=q3; y3.y*=q3; y3.z*=q3; y3.w*=q3;

    float* row = g_ay + (size_t)d*AYW;
    *(float4*)&row[lane*4]               = va;
    *(float4*)&row[128 + 0*128 + lane*4] = y0;
    *(float4*)&row[128 + 1*128 + lane*4] = y1;
    *(float4*)&row[128 + 2*128 + lane*4] = y2;
    *(float4*)&row[128 + 3*128 + lane*4] = y3;
    if (lane == 0)      row[640] = (end > beg) ? 1.f : 0.f;
    else if (lane < 16) row[640 + lane] = 0.f;
}

// ---------------- hyper aggregation + x copy (warp per node, CSR) ----------------
__global__ void aggregate_hyper(const float* __restrict__ ea, const float* __restrict__ x) {
    int w = (blockIdx.x * blockDim.x + threadIdx.x) >> 5;
    if (w >= NN) return;
    int lane = threadIdx.x & 31;
    int beg = g_offH[w], end = g_offH[w+1];
    float4 acc = make_float4(0.f,0.f,0.f,0.f);
    for (int idx = beg; idx < end; idx++) {
        int i = g_payH[idx];
        float4 eav = *(const float4*)&ea[(size_t)i*128 + lane*4];
        acc.x += eav.x; acc.y += eav.y; acc.z += eav.z; acc.w += eav.w;
    }
    int len = end - beg;
    float binv = (len > 0) ? (1.f / (float)len) : 0.f;
    acc.x *= binv; acc.y *= binv; acc.z *= binv; acc.w *= binv;
    *(float4*)&g_axh[(size_t)w*256 + lane*4] = acc;
    *(float4*)&g_axh[(size_t)w*256 + 128 + lane*4] = *(const float4*)&x[(size_t)w*128 + lane*4];
}

// ---------------- BatchNorm ----------------
__global__ void bn_stats() {
    __shared__ float ssum[8][CC], ssq[8][CC];
    int c  = threadIdx.x & 31;
    int ry = threadIdx.x >> 5;
    float s = 0.f, q = 0.f;
    for (int r = blockIdx.x * 8 + ry; r < NN; r += gridDim.x * 8) {
        float v = g_xgat[r*CC + c];
        s += v; q += v * v;
    }
    ssum[ry][c] = s; ssq[ry][c] = q;
    __syncthreads();
    if (ry == 0) {
        #pragma unroll
        for (int i = 1; i < 8; i++) { s += ssum[i][c]; q += ssq[i][c]; }
        atomicAdd(&g_sum[c],   (double)s);
        atomicAdd(&g_sumsq[c], (double)q);
    }
}

__global__ void bn_final() {
    int c = threadIdx.x;
    if (c < CC) {
        double mu  = g_sum[c] / (double)NN;
        double var = g_sumsq[c] / (double)NN - mu * mu;
        g_mu[c]   = (float)mu;
        g_rstd[c] = (float)(1.0 / sqrt(var + 1e-5));
    }
}

__global__ void bn_apply(const float* __restrict__ bn_w, const float* __restrict__ bn_b,
                         float* __restrict__ out1) {
    int i = blockIdx.x * blockDim.x + threadIdx.x;
    if (i >= NN*CC) return;
    int c = i & 31;
    float xn = bn_w[c] * (g_xgat[i] - g_mu[c]) * g_rstd[c] + bn_b[c];
    out1[i] = 0.5f * xn * (1.0f + erff(xn * 0.70710678118654752f));
}

// ---------------- hyper output ----------------
__global__ void hyper_out(const int* __restrict__ ei, const float* __restrict__ bh,
                          float* __restrict__ out2) {
    int idx = blockIdx.x * blockDim.x + threadIdx.x;
    if (idx >= E2*CC) return;
    int i = idx >> 5, c = idx & 31;
    out2[idx] = 0.5f * (g_o1[ei[i]*CC + c] + g_o1[ei[EE + i]*CC + c]) + bh[c];
}

// ---------------- launcher ----------------
extern "C" void kernel_launch(void* const* d_in, const int* in_sizes, int n_in,
                              void* d_out, int out_size) {
    const float* x    = (const float*)d_in[0];
    const float* ea   = (const float*)d_in[1];
    const float* Wq   = (const float*)d_in[2];
    const float* bq   = (const float*)d_in[3];
    const float* Wk   = (const float*)d_in[4];
    const float* bk   = (const float*)d_in[5];
    const float* Wv   = (const float*)d_in[6];
    const float* bv   = (const float*)d_in[7];
    const float* We2  = (const float*)d_in[8];
    const float* be2  = (const float*)d_in[9];
    const float* We3  = (const float*)d_in[10];
    const float* be3  = (const float*)d_in[11];
    const float* Wcon = (const float*)d_in[12];
    const float* bn_w = (const float*)d_in[13];
    const float* bn_b = (const float*)d_in[14];
    const float* Wh1  = (const float*)d_in[15];
    const float* Wh2  = (const float*)d_in[16];
    const float* bh   = (const float*)d_in[17];
    const int*   ei   = (const int*)d_in[18];

    float* out  = (float*)d_out;
    float* out1 = out;
    float* out2 = out + (size_t)NN * CC;

    float *pq, *pk, *pv, *pay, *paxh, *pwbig, *pwh, *pxgat, *po1;
    int *pcntA, *pcntH, *poffA, *poffH, *pcurA, *pcurH, *pblkA, *pblkH;
    cudaGetSymbolAddress((void**)&pq,    g_q);
    cudaGetSymbolAddress((void**)&pk,    g_k);
    cudaGetSymbolAddress((void**)&pv,    g_v);
    cudaGetSymbolAddress((void**)&pay,   g_ay);
    cudaGetSymbolAddress((void**)&paxh,  g_axh);
    cudaGetSymbolAddress((void**)&pwbig, g_wbig);
    cudaGetSymbolAddress((void**)&pwh,   g_wh);
    cudaGetSymbolAddress((void**)&pxgat, g_xgat);
    cudaGetSymbolAddress((void**)&po1,   g_o1);
    cudaGetSymbolAddress((void**)&pcntA, g_cntA);
    cudaGetSymbolAddress((void**)&pcntH, g_cntH);
    cudaGetSymbolAddress((void**)&poffA, g_offA);
    cudaGetSymbolAddress((void**)&poffH, g_offH);
    cudaGetSymbolAddress((void**)&pcurA, g_curA);
    cudaGetSymbolAddress((void**)&pcurH, g_curH);
    cudaGetSymbolAddress((void**)&pblkA, g_blkA);
    cudaGetSymbolAddress((void**)&pblkH, g_blkH);

    const int U_SMEM = (128*132 + GN*128) * 4;
    cudaFuncSetAttribute(compute_u, cudaFuncAttributeMaxDynamicSharedMemorySize, U_SMEM);

    zero_kernel<<<256, 256>>>();
    transpose_we2<<<64, 256>>>(We2);
    prep_weights<<<(AYW*CC + 256*CC + 255)/256, 256>>>(Wcon, We3, be3, Wh1, Wh2);

    // CSR build
    csr_count<<<(EE + 255)/256, 256>>>(ei);
    scan1<<<NB_SCAN, 1024>>>(pcntA, poffA, pblkA);
    scan1<<<NB_SCAN, 1024>>>(pcntH, poffH, pblkH);
    scan2<<<1, 32>>>(pblkA);
    scan2<<<1, 32>>>(pblkH);
    scan3<<<(NN + 255)/256, 256>>>(poffA, pcurA, pblkA);
    scan3<<<(NN + 255)/256, 256>>>(poffH, pcurH, pblkH);
    csr_fill<<<(EE + 255)/256, 256>>>(ei);

    // node projections
    dim3 gN(1, (NN + 127) / 128);
    gemm_bias<128,128,16,8,8><<<gN, 256>>>(x, Wq, bq, pq, NN, HC, DINF);
    gemm_bias<128,128,16,8,8><<<gN, 256>>>(x, Wk, bk, pk, NN, HC, DINF);
    gemm_bias<128,128,16,8,8><<<gN, 256>>>(x, Wv, bv, pv, NN, HC, DINF);

    // u precompute
    compute_u<<<(NN + GN - 1)/GN, 256, U_SMEM>>>();

    // fused single-pass attention
    attn_fused<<<(NN*32 + 255)/256, 256>>>(ei, ea, be2);

    // x_gat = [va | y | ind] @ Wbig
    gemm_bias<128,32,16,4,4><<<dim3(1, (NN + 127)/128), 256>>>(pay, pwbig, nullptr, pxgat, NN, CC, AYW);

    // batchnorm + gelu -> out1
    bn_stats<<<256, 256>>>();
    bn_final<<<1, 32>>>();
    bn_apply<<<(NN * CC + 255) / 256, 256>>>(bn_w, bn_b, out1);

    // hypergraph branch
    aggregate_hyper<<<(NN*32 + 255)/256, 256>>>(ea, x);
    gemm_bias<128,32,16,4,4><<<dim3(1, (NN + 127)/128), 256>>>(paxh, pwh, nullptr, po1, NN, CC, 256);
    hyper_out<<<(E2 * CC + 255) / 256, 256>>>(ei, bh, out2);
}

// round 6
// speedup vs baseline: 3.5608x; 1.0964x over previous
#include <cuda_runtime.h>
#include <math.h>
#include <stdint.h>

#define NN 50000
#define EE 512000
#define E2 (EE/2)
#define DINF 128
#define HC 128
#define CC 32
#define HH 4
#define AYW 656   // 128 va | 512 y | 1 ind | 15 pad
#define NB_SCAN ((NN + 1023) / 1024)

// ---------------- scratch ----------------
__device__ float    g_q[NN*HC];
__device__ float    g_k[NN*HC];
__device__ float    g_v[NN*HC];
__device__ float    g_u[(size_t)NN*HH*DINF];   // u[n][h][f]
__device__ float    g_we2t[DINF*HC];
__device__ float    g_ay[(size_t)NN*AYW];      // [va | y | ind | pad]
__device__ float    g_axh[(size_t)NN*256];     // [se_scaled | x]
__device__ float    g_wbig[AYW*CC];            // [Wcon; Wfold; bc; 0]
__device__ float    g_wh[256*CC];              // [Wh1; Wh2]
__device__ float    g_xgat[NN*CC];
__device__ float    g_o1[NN*CC];
__device__ double   g_sum[CC];
__device__ double   g_sumsq[CC];
__device__ float    g_mu[CC];
__device__ float    g_rstd[CC];
// CSR
__device__ int      g_cntA[NN];
__device__ int      g_cntH[NN];
__device__ int      g_offA[NN+1];
__device__ int      g_offH[NN+1];
__device__ int      g_curA[NN];
__device__ int      g_curH[NN];
__device__ int      g_payA[EE];
__device__ int      g_payH[EE];
__device__ int      g_blkA[NB_SCAN+1];
__device__ int      g_blkH[NB_SCAN+1];

// ---------------- f32x2 helpers ----------------
__device__ __forceinline__ unsigned long long pack2(float lo, float hi) {
    unsigned long long r;
    asm("mov.b64 %0, {%1, %2};" : "=l"(r) : "f"(lo), "f"(hi));
    return r;
}
__device__ __forceinline__ void fma2(unsigned long long& d, unsigned long long a, unsigned long long b) {
    asm("fma.rn.f32x2 %0, %1, %2, %0;" : "+l"(d) : "l"(a), "l"(b));
}
__device__ __forceinline__ float2 unpack2(unsigned long long v) {
    float lo, hi;
    asm("mov.b64 {%0, %1}, %2;" : "=f"(lo), "=f"(hi) : "l"(v));
    return make_float2(lo, hi);
}

// ---------------- zero scratch ----------------
__global__ void zero_kernel() {
    int i = blockIdx.x * blockDim.x + threadIdx.x;
    int stride = gridDim.x * blockDim.x;
    for (int j = i; j < NN; j += stride) { g_cntA[j]=0; g_cntH[j]=0; }
    if (i < CC) { g_sum[i]=0.0; g_sumsq[i]=0.0; }
}

__global__ void transpose_we2(const float* __restrict__ We2) {
    int i = blockIdx.x * blockDim.x + threadIdx.x;
    if (i < DINF*HC) {
        int f = i >> 7, o = i & 127;
        g_we2t[o*DINF + f] = We2[i];
    }
}

// ---------------- weight prep ----------------
__global__ void prep_weights(const float* __restrict__ Wcon, const float* __restrict__ We3,
                             const float* __restrict__ be3,
                             const float* __restrict__ Wh1, const float* __restrict__ Wh2) {
    int idx = blockIdx.x * blockDim.x + threadIdx.x;
    int total = AYW*CC + 256*CC;
    if (idx >= total) return;
    if (idx < AYW*CC) {
        int r = idx / CC, c = idx % CC;
        float v;
        if (r < 128) {
            v = Wcon[r*CC + c];
        } else if (r < 640) {
            int h = (r - 128) >> 7, f = (r - 128) & 127;
            float a = 0.f;
            #pragma unroll
            for (int c2 = 0; c2 < 32; c2++)
                a = fmaf(We3[f*HC + h*32 + c2], Wcon[(h*32 + c2)*CC + c], a);
            v = a;
        } else if (r == 640) {
            float a = 0.f;
            for (int k = 0; k < HC; k++)
                a = fmaf(be3[k], Wcon[k*CC + c], a);
            v = a;
        } else v = 0.f;
        g_wbig[r*CC + c] = v;
    } else {
        int j = idx - AYW*CC;
        int r = j / CC, c = j % CC;
        g_wh[r*CC + c] = (r < 128) ? Wh1[r*CC + c] : Wh2[(r-128)*CC + c];
    }
}

// ---------------- CSR build ----------------
__global__ void csr_count(const int* __restrict__ ei) {
    int i = blockIdx.x * blockDim.x + threadIdx.x;
    if (i >= EE) return;
    atomicAdd(&g_cntA[ei[EE + i]], 1);
    if (i < E2) {
        atomicAdd(&g_cntH[ei[i]],      1);
        atomicAdd(&g_cntH[ei[EE + i]], 1);
    }
}

__global__ void scan1(const int* __restrict__ cnt, int* __restrict__ off, int* __restrict__ blk) {
    __shared__ int sd[1024];
    int tid = threadIdx.x;
    int i = blockIdx.x * 1024 + tid;
    int v = (i < NN) ? cnt[i] : 0;
    sd[tid] = v;
    __syncthreads();
    #pragma unroll
    for (int ofs = 1; ofs < 1024; ofs <<= 1) {
        int t = (tid >= ofs) ? sd[tid - ofs] : 0;
        __syncthreads();
        sd[tid] += t;
        __syncthreads();
    }
    if (i < NN) off[i] = sd[tid] - v;
    if (tid == 1023) blk[blockIdx.x] = sd[1023];
}

__global__ void scan2(int* __restrict__ blk) {
    if (threadIdx.x == 0) {
        int run = 0;
        for (int b = 0; b < NB_SCAN; b++) { int t = blk[b]; blk[b] = run; run += t; }
        blk[NB_SCAN] = run;
    }
}

__global__ void scan3(int* __restrict__ off, int* __restrict__ cur, const int* __restrict__ blk) {
    int i = blockIdx.x * blockDim.x + threadIdx.x;
    if (i < NN) {
        int o = off[i] + blk[i >> 10];
        off[i] = o;
        cur[i] = o;
    }
    if (i == 0) off[NN] = blk[NB_SCAN];
}

__global__ void csr_fill(const int* __restrict__ ei) {
    int i = blockIdx.x * blockDim.x + threadIdx.x;
    if (i >= EE) return;
    int d = ei[EE + i];
    int pos = atomicAdd(&g_curA[d], 1);
    g_payA[pos] = i;
    if (i < E2) {
        int p1 = atomicAdd(&g_curH[ei[i]], 1);
        g_payH[p1] = i;
        int p2 = atomicAdd(&g_curH[ei[EE + i]], 1);
        g_payH[p2] = i;
    }
}

// ---------------- double-buffered SGEMM with f32x2 accumulation ----------------
template<int BM, int BN, int BK, int TM, int TN>
__global__ void __launch_bounds__((BM/TM)*(BN/TN), 2)
gemm_bias(const float* __restrict__ A, const float* __restrict__ W,
          const float* __restrict__ bias, float* __restrict__ C,
          int M, int N, int K) {
    constexpr int THREADS = (BM/TM)*(BN/TN);
    constexpr int A4 = BM*BK/4;
    constexpr int W4 = BK*BN/4;
    constexpr int AI = (A4 + THREADS - 1)/THREADS;
    constexpr int WI = (W4 + THREADS - 1)/THREADS;
    __shared__ float As[2][BK][BM+4];
    __shared__ float Ws[2][BK][BN];
    const int tid  = threadIdx.x;
    const int brow = blockIdx.y * BM;
    const int bcol = blockIdx.x * BN;
    const int trow = (tid / (BN/TN)) * TM;
    const int tcol = (tid % (BN/TN)) * TN;

    float4 stA[AI];
    float4 stW[WI];

    auto loadg = [&](int k0) {
        #pragma unroll
        for (int it = 0; it < AI; it++) {
            int i = tid + it*THREADS;
            if (i < A4) {
                int m = i / (BK/4), k4 = i % (BK/4);
                int gm = brow + m;
                stA[it] = (gm < M) ? *(const float4*)(A + (size_t)gm*K + k0 + k4*4)
                                   : make_float4(0.f,0.f,0.f,0.f);
            }
        }
        #pragma unroll
        for (int it = 0; it < WI; it++) {
            int i = tid + it*THREADS;
            if (i < W4) {
                int kk = i / (BN/4), n4 = i % (BN/4);
                stW[it] = *(const float4*)(W + (size_t)(k0+kk)*N + bcol + n4*4);
            }
        }
    };
    auto store_s = [&](int buf) {
        #pragma unroll
        for (int it = 0; it < AI; it++) {
            int i = tid + it*THREADS;
            if (i < A4) {
                int m = i / (BK/4), k4 = i % (BK/4);
                As[buf][k4*4+0][m] = stA[it].x;
                As[buf][k4*4+1][m] = stA[it].y;
                As[buf][k4*4+2][m] = stA[it].z;
                As[buf][k4*4+3][m] = stA[it].w;
            }
        }
        #pragma unroll
        for (int it = 0; it < WI; it++) {
            int i = tid + it*THREADS;
            if (i < W4) {
                int kk = i / (BN/4), n4 = i % (BN/4);
                *(float4*)&Ws[buf][kk][n4*4] = stW[it];
            }
        }
    };

    unsigned long long acc2[TM][TN/2];
    #pragma unroll
    for (int i = 0; i < TM; i++)
        #pragma unroll
        for (int j = 0; j < TN/2; j++) acc2[i][j] = 0ULL;

    const int nt = K / BK;
    loadg(0);
    store_s(0);
    __syncthreads();

    for (int t = 0; t < nt; t++) {
        int cur = t & 1;
        if (t + 1 < nt) loadg((t+1)*BK);
        #pragma unroll
        for (int kk = 0; kk < BK; kk++) {
            float ra[TM], rb[TN];
            #pragma unroll
            for (int i = 0; i < TM; i += 4)
                *(float4*)&ra[i] = *(const float4*)&As[cur][kk][trow + i];
            #pragma unroll
            for (int j = 0; j < TN; j += 4)
                *(float4*)&rb[j] = *(const float4*)&Ws[cur][kk][tcol + j];
            unsigned long long rbp[TN/2];
            #pragma unroll
            for (int j = 0; j < TN/2; j++) rbp[j] = pack2(rb[2*j], rb[2*j+1]);
            #pragma unroll
            for (int i = 0; i < TM; i++) {
                unsigned long long aa = pack2(ra[i], ra[i]);
                #pragma unroll
                for (int j = 0; j < TN/2; j++)
                    fma2(acc2[i][j], aa, rbp[j]);
            }
        }
        if (t + 1 < nt) {
            store_s((t+1) & 1);
            __syncthreads();
        }
    }

    #pragma unroll
    for (int i = 0; i < TM; i++) {
        int gm = brow + trow + i;
        if (gm >= M) continue;
        #pragma unroll
        for (int j = 0; j < TN; j += 4) {
            int gn = bcol + tcol + j;
            float2 p0 = unpack2(acc2[i][j/2]);
            float2 p1 = unpack2(acc2[i][j/2 + 1]);
            float4 v;
            v.x = p0.x + (bias ? bias[gn+0] : 0.f);
            v.y = p0.y + (bias ? bias[gn+1] : 0.f);
            v.z = p1.x + (bias ? bias[gn+2] : 0.f);
            v.w = p1.y + (bias ? bias[gn+3] : 0.f);
            *(float4*)(C + (size_t)gm*N + gn) = v;
        }
    }
}

// ---------------- dual small GEMM (N=32): both output projections in one launch ----------------
__device__ __forceinline__ void gemm_body32(const float* __restrict__ A, const float* __restrict__ W,
                                            float* __restrict__ C, int K, int browblk) {
    // BM=128, BN=32, BK=16, TM=4, TN=4, 256 threads
    __shared__ float As[2][16][132];
    __shared__ float Ws[2][16][32];
    const int tid  = threadIdx.x;
    const int brow = browblk * 128;
    const int trow = (tid / 8) * 4;
    const int tcol = (tid % 8) * 4;

    float4 stA[2];
    float4 stW;

    auto loadg = [&](int k0) {
        #pragma unroll
        for (int it = 0; it < 2; it++) {
            int i = tid + it*256;
            int m = i / 4, k4 = i % 4;
            int gm = brow + m;
            stA[it] = (gm < NN) ? *(const float4*)(A + (size_t)gm*K + k0 + k4*4)
                                : make_float4(0.f,0.f,0.f,0.f);
        }
        if (tid < 128) {
            int kk = tid / 8, n4 = tid % 8;
            stW = *(const float4*)(W + (size_t)(k0+kk)*32 + n4*4);
        }
    };
    auto store_s = [&](int buf) {
        #pragma unroll
        for (int it = 0; it < 2; it++) {
            int i = tid + it*256;
            int m = i / 4, k4 = i % 4;
            As[buf][k4*4+0][m] = stA[it].x;
            As[buf][k4*4+1][m] = stA[it].y;
            As[buf][k4*4+2][m] = stA[it].z;
            As[buf][k4*4+3][m] = stA[it].w;
        }
        if (tid < 128) {
            int kk = tid / 8, n4 = tid % 8;
            *(float4*)&Ws[buf][kk][n4*4] = stW;
        }
    };

    unsigned long long acc2[4][2];
    #pragma unroll
    for (int i = 0; i < 4; i++) { acc2[i][0] = 0ULL; acc2[i][1] = 0ULL; }

    const int nt = K / 16;
    loadg(0);
    store_s(0);
    __syncthreads();

    for (int t = 0; t < nt; t++) {
        int cur = t & 1;
        if (t + 1 < nt) loadg((t+1)*16);
        #pragma unroll
        for (int kk = 0; kk < 16; kk++) {
            float ra[4], rb[4];
            *(float4*)&ra[0] = *(const float4*)&As[cur][kk][trow];
            *(float4*)&rb[0] = *(const float4*)&Ws[cur][kk][tcol];
            unsigned long long rbp0 = pack2(rb[0], rb[1]);
            unsigned long long rbp1 = pack2(rb[2], rb[3]);
            #pragma unroll
            for (int i = 0; i < 4; i++) {
                unsigned long long aa = pack2(ra[i], ra[i]);
                fma2(acc2[i][0], aa, rbp0);
                fma2(acc2[i][1], aa, rbp1);
            }
        }
        if (t + 1 < nt) {
            store_s((t+1) & 1);
            __syncthreads();
        }
    }

    #pragma unroll
    for (int i = 0; i < 4; i++) {
        int gm = brow + trow + i;
        if (gm >= NN) continue;
        float2 p0 = unpack2(acc2[i][0]);
        float2 p1 = unpack2(acc2[i][1]);
        float4 v = make_float4(p0.x, p0.y, p1.x, p1.y);
        *(float4*)(C + (size_t)gm*32 + tcol) = v;
    }
}

#define NB32 ((NN + 127) / 128)
__global__ void __launch_bounds__(256, 2) gemm_dual() {
    bool second = blockIdx.y >= NB32;
    const float* A = second ? g_axh : g_ay;
    const float* W = second ? g_wh  : g_wbig;
    float*       C = second ? g_o1  : g_xgat;
    int          K = second ? 256   : AYW;
    int        blk = second ? (blockIdx.y - NB32) : blockIdx.y;
    gemm_body32(A, W, C, K, blk);
}

// ---------------- u precompute ----------------
#define GN 32
__global__ void compute_u() {
    extern __shared__ float shm[];
    float (*sW)[132] = (float (*)[132])shm;
    float (*sq)[128] = (float (*)[128])(shm + 128*132);
    int tid = threadIdx.x;
    int n0 = blockIdx.x * GN;
    for (int i = tid; i < 128*128; i += 256) {
        int o = i >> 7, f = i & 127;
        sW[o][f] = g_we2t[i];
    }
    for (int i = tid; i < GN*128; i += 256) {
        int nl = i >> 7, c = i & 127;
        int n = n0 + nl;
        sq[nl][c] = (n < NN) ? g_q[(size_t)n*128 + c] : 0.f;
    }
    __syncthreads();
    int w = tid >> 5, lane = tid & 31;
    for (int p = w; p < GN*HH; p += 8) {
        int nl = p >> 2, h = p & 3;
        int n = n0 + nl;
        if (n >= NN) continue;
        float a0=0.f, a1=0.f, a2=0.f, a3=0.f;
        #pragma unroll
        for (int c = 0; c < 32; c++) {
            float qv = sq[nl][h*32 + c];
            const float* row = sW[h*32 + c];
            a0 = fmaf(qv, row[lane],      a0);
            a1 = fmaf(qv, row[lane + 32], a1);
            a2 = fmaf(qv, row[lane + 64], a2);
            a3 = fmaf(qv, row[lane + 96], a3);
        }
        size_t base = (size_t)n*512 + h*128;
        g_u[base + lane]      = a0;
        g_u[base + lane + 32] = a1;
        g_u[base + lane + 64] = a2;
        g_u[base + lane + 96] = a3;
    }
}

// ---------------- fused edge kernel: even blocks = attention, odd blocks = hyper agg ----------------
__global__ void edge_fused(const int* __restrict__ ei, const float* __restrict__ ea,
                           const float* __restrict__ be2, const float* __restrict__ x) {
    const unsigned FULL = 0xffffffffu;
    const int lane = threadIdx.x & 31;
    const int node = (blockIdx.x >> 1) * 8 + (threadIdx.x >> 5);
    if (node >= NN) return;

    if ((blockIdx.x & 1) == 0) {
        // ---- attention: warp per dst node ----
        const int g = lane >> 3, sub = lane & 7;
        const int d = node;
        const int beg = g_offA[d], end = g_offA[d+1];
        const float scale = 0.17677669529663687f;

        float4 qv = *(const float4*)&g_q[(size_t)d*HC + g*32 + sub*4];
        float4 b2 = *(const float4*)&be2[g*32 + sub*4];
        float qb2 = qv.x*b2.x + qv.y*b2.y + qv.z*b2.z + qv.w*b2.w;
        float4 u4[4];
        #pragma unroll
        for (int j = 0; j < 4; j++)
            u4[j] = *(const float4*)&g_u[(size_t)d*512 + g*128 + sub*16 + j*4];

        float4 va = make_float4(0.f,0.f,0.f,0.f);
        float4 y0 = va, y1 = va, y2 = va, y3 = va;
        float s1 = 0.f, s20 = 0.f, s21 = 0.f, s22 = 0.f, s23 = 0.f;

        for (int base = beg; base < end; base += 32) {
            int m = end - base; if (m > 32) m = 32;
            int eL = 0, sL = 0;
            if (base + lane < end) {
                eL = g_payA[base + lane];
                sL = ei[eL];
            }
            for (int it = 0; it < m; it++) {
                int e = __shfl_sync(FULL, eL, it);
                int s = __shfl_sync(FULL, sL, it);
                const float* eb = ea + (size_t)e*128;

                float4 ka = *(const float4*)&g_k[(size_t)s*HC + g*32 + sub*4];
                float p1 = qv.x*ka.x + qv.y*ka.y + qv.z*ka.z + qv.w*ka.w;
                float p2 = qb2;
                #pragma unroll
                for (int j = 0; j < 4; j++) {
                    float4 ev = *(const float4*)&eb[sub*16 + j*4];
                    p2 += ev.x*u4[j].x + ev.y*u4[j].y + ev.z*u4[j].z + ev.w*u4[j].w;
                }
                #pragma unroll
                for (int o = 1; o < 8; o <<= 1) {
                    p1 += __shfl_xor_sync(FULL, p1, o);
                    p2 += __shfl_xor_sync(FULL, p2, o);
                }
                float ex1 = __expf(p1 * scale);
                float ex2 = __expf(p2 * scale);
                s1 += ex1;
                float e20 = __shfl_sync(FULL, ex2, 0);
                float e21 = __shfl_sync(FULL, ex2, 8);
                float e22 = __shfl_sync(FULL, ex2, 16);
                float e23 = __shfl_sync(FULL, ex2, 24);
                s20 += e20; s21 += e21; s22 += e22; s23 += e23;

                float4 eay = *(const float4*)&eb[lane*4];
                float4 vv  = *(const float4*)&g_v[(size_t)s*HC + lane*4];
                va.x = fmaf(ex1, vv.x, va.x); va.y = fmaf(ex1, vv.y, va.y);
                va.z = fmaf(ex1, vv.z, va.z); va.w = fmaf(ex1, vv.w, va.w);
                y0.x = fmaf(e20, eay.x, y0.x); y0.y = fmaf(e20, eay.y, y0.y);
                y0.z = fmaf(e20, eay.z, y0.z); y0.w = fmaf(e20, eay.w, y0.w);
                y1.x = fmaf(e21, eay.x, y1.x); y1.y = fmaf(e21, eay.y, y1.y);
                y1.z = fmaf(e21, eay.z, y1.z); y1.w = fmaf(e21, eay.w, y1.w);
                y2.x = fmaf(e22, eay.x, y2.x); y2.y = fmaf(e22, eay.y, y2.y);
                y2.z = fmaf(e22, eay.z, y2.z); y2.w = fmaf(e22, eay.w, y2.w);
                y3.x = fmaf(e23, eay.x, y3.x); y3.y = fmaf(e23, eay.y, y3.y);
                y3.z = fmaf(e23, eay.z, y3.z); y3.w = fmaf(e23, eay.w, y3.w);
            }
        }

        float r1 = 1.f / (s1 + 1e-16f);
        va.x *= r1; va.y *= r1; va.z *= r1; va.w *= r1;
        float q0 = 1.f/(s20+1e-16f), q1 = 1.f/(s21+1e-16f);
        float q2 = 1.f/(s22+1e-16f), q3 = 1.f/(s23+1e-16f);
        y0.x*=q0; y0.y*=q0; y0.z*=q0; y0.w*=q0;
        y1.x*=q1; y1.y*=q1; y1.z*=q1; y1.w*=q1;
        y2.x*=q2; y2.y*=q2; y2.z*=q2; y2.w*=q2;
        y3.x*=q3; y3.y*=q3; y3.z*=q3; y3.w*=q3;

        float* row = g_ay + (size_t)d*AYW;
        *(float4*)&row[lane*4]               = va;
        *(float4*)&row[128 + 0*128 + lane*4] = y0;
        *(float4*)&row[128 + 1*128 + lane*4] = y1;
        *(float4*)&row[128 + 2*128 + lane*4] = y2;
        *(float4*)&row[128 + 3*128 + lane*4] = y3;
        if (lane == 0)      row[640] = (end > beg) ? 1.f : 0.f;
        else if (lane < 16) row[640 + lane] = 0.f;
    } else {
        // ---- hyper aggregation: warp per node ----
        const int n = node;
        const int beg = g_offH[n], end = g_offH[n+1];
        float4 acc = make_float4(0.f,0.f,0.f,0.f);
        for (int base = beg; base < end; base += 32) {
            int m = end - base; if (m > 32) m = 32;
            int iL = 0;
            if (base + lane < end) iL = g_payH[base + lane];
            for (int it = 0; it < m; it++) {
                int i = __shfl_sync(FULL, iL, it);
                float4 eav = *(const float4*)&ea[(size_t)i*128 + lane*4];
                acc.x += eav.x; acc.y += eav.y; acc.z += eav.z; acc.w += eav.w;
            }
        }
        int len = end - beg;
        float binv = (len > 0) ? (1.f / (float)len) : 0.f;
        acc.x *= binv; acc.y *= binv; acc.z *= binv; acc.w *= binv;
        *(float4*)&g_axh[(size_t)n*256 + lane*4] = acc;
        *(float4*)&g_axh[(size_t)n*256 + 128 + lane*4] = *(const float4*)&x[(size_t)n*128 + lane*4];
    }
}

// ---------------- merged bn_stats + hyper_out ----------------
__global__ void bn_hyper(const int* __restrict__ ei, const float* __restrict__ bh,
                         float* __restrict__ out2) {
    if (blockIdx.x < 256) {
        __shared__ float ssum[8][CC], ssq[8][CC];
        int c  = threadIdx.x & 31;
        int ry = threadIdx.x >> 5;
        float s = 0.f, q = 0.f;
        for (int r = blockIdx.x * 8 + ry; r < NN; r += 256 * 8) {
            float v = g_xgat[r*CC + c];
            s += v; q += v * v;
        }
        ssum[ry][c] = s; ssq[ry][c] = q;
        __syncthreads();
        if (ry == 0) {
            #pragma unroll
            for (int i = 1; i < 8; i++) { s += ssum[i][c]; q += ssq[i][c]; }
            atomicAdd(&g_sum[c],   (double)s);
            atomicAdd(&g_sumsq[c], (double)q);
        }
    } else {
        int idx = (blockIdx.x - 256) * 256 + threadIdx.x;
        if (idx >= E2*CC) return;
        int i = idx >> 5, c = idx & 31;
        out2[idx] = 0.5f * (g_o1[ei[i]*CC + c] + g_o1[ei[EE + i]*CC + c]) + bh[c];
    }
}

__global__ void bn_final() {
    int c = threadIdx.x;
    if (c < CC) {
        double mu  = g_sum[c] / (double)NN;
        double var = g_sumsq[c] / (double)NN - mu * mu;
        g_mu[c]   = (float)mu;
        g_rstd[c] = (float)(1.0 / sqrt(var + 1e-5));
    }
}

__global__ void bn_apply(const float* __restrict__ bn_w, const float* __restrict__ bn_b,
                         float* __restrict__ out1) {
    int i = blockIdx.x * blockDim.x + threadIdx.x;
    if (i >= NN*CC) return;
    int c = i & 31;
    float xn = bn_w[c] * (g_xgat[i] - g_mu[c]) * g_rstd[c] + bn_b[c];
    out1[i] = 0.5f * xn * (1.0f + erff(xn * 0.70710678118654752f));
}

// ---------------- launcher ----------------
extern "C" void kernel_launch(void* const* d_in, const int* in_sizes, int n_in,
                              void* d_out, int out_size) {
    const float* x    = (const float*)d_in[0];
    const float* ea   = (const float*)d_in[1];
    const float* Wq   = (const float*)d_in[2];
    const float* bq   = (const float*)d_in[3];
    const float* Wk   = (const float*)d_in[4];
    const float* bk   = (const float*)d_in[5];
    const float* Wv   = (const float*)d_in[6];
    const float* bv   = (const float*)d_in[7];
    const float* We2  = (const float*)d_in[8];
    const float* be2  = (const float*)d_in[9];
    const float* We3  = (const float*)d_in[10];
    const float* be3  = (const float*)d_in[11];
    const float* Wcon = (const float*)d_in[12];
    const float* bn_w = (const float*)d_in[13];
    const float* bn_b = (const float*)d_in[14];
    const float* Wh1  = (const float*)d_in[15];
    const float* Wh2  = (const float*)d_in[16];
    const float* bh   = (const float*)d_in[17];
    const int*   ei   = (const int*)d_in[18];

    float* out  = (float*)d_out;
    float* out1 = out;
    float* out2 = out + (size_t)NN * CC;

    float *pq, *pk, *pv;
    int *pcntA, *pcntH, *poffA, *poffH, *pcurA, *pcurH, *pblkA, *pblkH;
    cudaGetSymbolAddress((void**)&pq,    g_q);
    cudaGetSymbolAddress((void**)&pk,    g_k);
    cudaGetSymbolAddress((void**)&pv,    g_v);
    cudaGetSymbolAddress((void**)&pcntA, g_cntA);
    cudaGetSymbolAddress((void**)&pcntH, g_cntH);
    cudaGetSymbolAddress((void**)&poffA, g_offA);
    cudaGetSymbolAddress((void**)&poffH, g_offH);
    cudaGetSymbolAddress((void**)&pcurA, g_curA);
    cudaGetSymbolAddress((void**)&pcurH, g_curH);
    cudaGetSymbolAddress((void**)&pblkA, g_blkA);
    cudaGetSymbolAddress((void**)&pblkH, g_blkH);

    const int U_SMEM = (128*132 + GN*128) * 4;
    cudaFuncSetAttribute(compute_u, cudaFuncAttributeMaxDynamicSharedMemorySize, U_SMEM);

    zero_kernel<<<256, 256>>>();
    transpose_we2<<<64, 256>>>(We2);
    prep_weights<<<(AYW*CC + 256*CC + 255)/256, 256>>>(Wcon, We3, be3, Wh1, Wh2);

    // CSR build
    csr_count<<<(EE + 255)/256, 256>>>(ei);
    scan1<<<NB_SCAN, 1024>>>(pcntA, poffA, pblkA);
    scan1<<<NB_SCAN, 1024>>>(pcntH, poffH, pblkH);
    scan2<<<1, 32>>>(pblkA);
    scan2<<<1, 32>>>(pblkH);
    scan3<<<(NN + 255)/256, 256>>>(poffA, pcurA, pblkA);
    scan3<<<(NN + 255)/256, 256>>>(poffH, pcurH, pblkH);
    csr_fill<<<(EE + 255)/256, 256>>>(ei);

    // node projections (f32x2 GEMM)
    dim3 gN(1, (NN + 127) / 128);
    gemm_bias<128,128,16,8,8><<<gN, 256>>>(x, Wq, bq, pq, NN, HC, DINF);
    gemm_bias<128,128,16,8,8><<<gN, 256>>>(x, Wk, bk, pk, NN, HC, DINF);
    gemm_bias<128,128,16,8,8><<<gN, 256>>>(x, Wv, bv, pv, NN, HC, DINF);

    // u precompute
    compute_u<<<(NN + GN - 1)/GN, 256, U_SMEM>>>();

    // fused attention + hyper aggregation
    edge_fused<<<2 * ((NN + 7)/8), 256>>>(ei, ea, be2, x);

    // both output projections in one launch
    gemm_dual<<<dim3(1, 2*NB32), 256>>>();

    // bn stats + hyper edge output in one launch
    bn_hyper<<<256 + (E2*CC + 255)/256, 256>>>(ei, bh, out2);
    bn_final<<<1, 32>>>();
    bn_apply<<<(NN * CC + 255) / 256, 256>>>(bn_w, bn_b, out1);
}

// round 7
// speedup vs baseline: 3.6943x; 1.0375x over previous
#include <cuda_runtime.h>
#include <math.h>
#include <stdint.h>

#define NN 50000
#define EE 512000
#define E2 (EE/2)
#define DINF 128
#define HC 128
#define CC 32
#define HH 4
#define AYW 656   // 128 va | 512 y | 1 ind | 15 pad
#define QS 384    // qkv packed row stride
#define NB_SCAN ((NN + 1023) / 1024)

// ---------------- scratch ----------------
__device__ float    g_qkv[(size_t)NN*QS];      // [q | k | v] per node
__device__ float    g_wqkv[DINF*QS];
__device__ float    g_bqkv[QS];
__device__ float    g_u[(size_t)NN*HH*DINF];   // u[n][h][f]
__device__ float    g_we2t[DINF*HC];
__device__ float    g_ay[(size_t)NN*AYW];      // [va | y | ind | pad]
__device__ float    g_axh[(size_t)NN*256];     // [se_scaled | x]
__device__ float    g_wbig[AYW*CC];            // [Wcon; Wfold; bc; 0]
__device__ float    g_wh[256*CC];              // [Wh1; Wh2]
__device__ float    g_xgat[NN*CC];
__device__ float    g_o1[NN*CC];
__device__ double   g_sum[CC];
__device__ double   g_sumsq[CC];
__device__ float    g_mu[CC];
__device__ float    g_rstd[CC];
// CSR
__device__ int      g_cntA[NN];
__device__ int      g_cntH[NN];
__device__ int      g_offA[NN+1];
__device__ int      g_offH[NN+1];
__device__ int      g_curA[NN];
__device__ int      g_curH[NN];
__device__ int      g_payA[EE];
__device__ int      g_payH[EE];
__device__ int      g_blkA[NB_SCAN+1];
__device__ int      g_blkH[NB_SCAN+1];

// ---------------- f32x2 helpers ----------------
__device__ __forceinline__ unsigned long long pack2(float lo, float hi) {
    unsigned long long r;
    asm("mov.b64 %0, {%1, %2};" : "=l"(r) : "f"(lo), "f"(hi));
    return r;
}
__device__ __forceinline__ void fma2(unsigned long long& d, unsigned long long a, unsigned long long b) {
    asm("fma.rn.f32x2 %0, %1, %2, %0;" : "+l"(d) : "l"(a), "l"(b));
}
__device__ __forceinline__ float2 unpack2(unsigned long long v) {
    float lo, hi;
    asm("mov.b64 {%0, %1}, %2;" : "=f"(lo), "=f"(hi) : "l"(v));
    return make_float2(lo, hi);
}

// ---------------- setup: zero + transposes + weight packing, one launch ----------------
__global__ void setup_kernel(const float* __restrict__ We2,
                             const float* __restrict__ Wcon, const float* __restrict__ We3,
                             const float* __restrict__ be3,
                             const float* __restrict__ Wh1, const float* __restrict__ Wh2,
                             const float* __restrict__ Wq, const float* __restrict__ bq,
                             const float* __restrict__ Wk, const float* __restrict__ bk,
                             const float* __restrict__ Wv, const float* __restrict__ bv) {
    int tid = blockIdx.x * blockDim.x + threadIdx.x;
    int stride = gridDim.x * blockDim.x;
    for (int j = tid; j < NN; j += stride) { g_cntA[j]=0; g_cntH[j]=0; }
    if (tid < CC) { g_sum[tid]=0.0; g_sumsq[tid]=0.0; }
    for (int i = tid; i < DINF*HC; i += stride) {
        int f = i >> 7, o = i & 127;
        g_we2t[o*DINF + f] = We2[i];
    }
    for (int idx = tid; idx < AYW*CC; idx += stride) {
        int r = idx / CC, c = idx % CC;
        float v;
        if (r < 128) {
            v = Wcon[r*CC + c];
        } else if (r < 640) {
            int h = (r - 128) >> 7, f = (r - 128) & 127;
            float a = 0.f;
            #pragma unroll
            for (int c2 = 0; c2 < 32; c2++)
                a = fmaf(We3[f*HC + h*32 + c2], Wcon[(h*32 + c2)*CC + c], a);
            v = a;
        } else if (r == 640) {
            float a = 0.f;
            for (int k = 0; k < HC; k++)
                a = fmaf(be3[k], Wcon[k*CC + c], a);
            v = a;
        } else v = 0.f;
        g_wbig[r*CC + c] = v;
    }
    for (int j = tid; j < 256*CC; j += stride) {
        int r = j / CC, c = j % CC;
        g_wh[r*CC + c] = (r < 128) ? Wh1[r*CC + c] : Wh2[(r-128)*CC + c];
    }
    for (int j = tid; j < DINF*QS; j += stride) {
        int f = j / QS, n = j % QS;
        float v = (n < 128) ? Wq[f*HC + n] : (n < 256) ? Wk[f*HC + n - 128] : Wv[f*HC + n - 256];
        g_wqkv[j] = v;
    }
    if (tid < QS) {
        g_bqkv[tid] = (tid < 128) ? bq[tid] : (tid < 256) ? bk[tid-128] : bv[tid-256];
    }
}

// ---------------- CSR build ----------------
__global__ void csr_count(const int* __restrict__ ei) {
    int i = blockIdx.x * blockDim.x + threadIdx.x;
    if (i >= EE) return;
    atomicAdd(&g_cntA[ei[EE + i]], 1);
    if (i < E2) {
        atomicAdd(&g_cntH[ei[i]],      1);
        atomicAdd(&g_cntH[ei[EE + i]], 1);
    }
}

__global__ void scan1(const int* __restrict__ cnt, int* __restrict__ off, int* __restrict__ blk) {
    __shared__ int sd[1024];
    int tid = threadIdx.x;
    int i = blockIdx.x * 1024 + tid;
    int v = (i < NN) ? cnt[i] : 0;
    sd[tid] = v;
    __syncthreads();
    #pragma unroll
    for (int ofs = 1; ofs < 1024; ofs <<= 1) {
        int t = (tid >= ofs) ? sd[tid - ofs] : 0;
        __syncthreads();
        sd[tid] += t;
        __syncthreads();
    }
    if (i < NN) off[i] = sd[tid] - v;
    if (tid == 1023) blk[blockIdx.x] = sd[1023];
}

__global__ void scan2(int* __restrict__ blk) {
    if (threadIdx.x == 0) {
        int run = 0;
        for (int b = 0; b < NB_SCAN; b++) { int t = blk[b]; blk[b] = run; run += t; }
        blk[NB_SCAN] = run;
    }
}

__global__ void scan3(int* __restrict__ off, int* __restrict__ cur, const int* __restrict__ blk) {
    int i = blockIdx.x * blockDim.x + threadIdx.x;
    if (i < NN) {
        int o = off[i] + blk[i >> 10];
        off[i] = o;
        cur[i] = o;
    }
    if (i == 0) off[NN] = blk[NB_SCAN];
}

__global__ void csr_fill(const int* __restrict__ ei) {
    int i = blockIdx.x * blockDim.x + threadIdx.x;
    if (i >= EE) return;
    int d = ei[EE + i];
    int pos = atomicAdd(&g_curA[d], 1);
    g_payA[pos] = i;
    if (i < E2) {
        int p1 = atomicAdd(&g_curH[ei[i]], 1);
        g_payH[p1] = i;
        int p2 = atomicAdd(&g_curH[ei[EE + i]], 1);
        g_payH[p2] = i;
    }
}

// ---------------- double-buffered SGEMM with f32x2 accumulation ----------------
template<int BM, int BN, int BK, int TM, int TN>
__global__ void __launch_bounds__((BM/TM)*(BN/TN), 2)
gemm_bias(const float* __restrict__ A, const float* __restrict__ W,
          const float* __restrict__ bias, float* __restrict__ C,
          int M, int N, int K) {
    constexpr int THREADS = (BM/TM)*(BN/TN);
    constexpr int A4 = BM*BK/4;
    constexpr int W4 = BK*BN/4;
    constexpr int AI = (A4 + THREADS - 1)/THREADS;
    constexpr int WI = (W4 + THREADS - 1)/THREADS;
    __shared__ float As[2][BK][BM+4];
    __shared__ float Ws[2][BK][BN];
    const int tid  = threadIdx.x;
    const int brow = blockIdx.y * BM;
    const int bcol = blockIdx.x * BN;
    const int trow = (tid / (BN/TN)) * TM;
    const int tcol = (tid % (BN/TN)) * TN;

    float4 stA[AI];
    float4 stW[WI];

    auto loadg = [&](int k0) {
        #pragma unroll
        for (int it = 0; it < AI; it++) {
            int i = tid + it*THREADS;
            if (i < A4) {
                int m = i / (BK/4), k4 = i % (BK/4);
                int gm = brow + m;
                stA[it] = (gm < M) ? *(const float4*)(A + (size_t)gm*K + k0 + k4*4)
                                   : make_float4(0.f,0.f,0.f,0.f);
            }
        }
        #pragma unroll
        for (int it = 0; it < WI; it++) {
            int i = tid + it*THREADS;
            if (i < W4) {
                int kk = i / (BN/4), n4 = i % (BN/4);
                stW[it] = *(const float4*)(W + (size_t)(k0+kk)*N + bcol + n4*4);
            }
        }
    };
    auto store_s = [&](int buf) {
        #pragma unroll
        for (int it = 0; it < AI; it++) {
            int i = tid + it*THREADS;
            if (i < A4) {
                int m = i / (BK/4), k4 = i % (BK/4);
                As[buf][k4*4+0][m] = stA[it].x;
                As[buf][k4*4+1][m] = stA[it].y;
                As[buf][k4*4+2][m] = stA[it].z;
                As[buf][k4*4+3][m] = stA[it].w;
            }
        }
        #pragma unroll
        for (int it = 0; it < WI; it++) {
            int i = tid + it*THREADS;
            if (i < W4) {
                int kk = i / (BN/4), n4 = i % (BN/4);
                *(float4*)&Ws[buf][kk][n4*4] = stW[it];
            }
        }
    };

    unsigned long long acc2[TM][TN/2];
    #pragma unroll
    for (int i = 0; i < TM; i++)
        #pragma unroll
        for (int j = 0; j < TN/2; j++) acc2[i][j] = 0ULL;

    const int nt = K / BK;
    loadg(0);
    store_s(0);
    __syncthreads();

    for (int t = 0; t < nt; t++) {
        int cur = t & 1;
        if (t + 1 < nt) loadg((t+1)*BK);
        #pragma unroll
        for (int kk = 0; kk < BK; kk++) {
            float ra[TM], rb[TN];
            #pragma unroll
            for (int i = 0; i < TM; i += 4)
                *(float4*)&ra[i] = *(const float4*)&As[cur][kk][trow + i];
            #pragma unroll
            for (int j = 0; j < TN; j += 4)
                *(float4*)&rb[j] = *(const float4*)&Ws[cur][kk][tcol + j];
            unsigned long long rbp[TN/2];
            #pragma unroll
            for (int j = 0; j < TN/2; j++) rbp[j] = pack2(rb[2*j], rb[2*j+1]);
            #pragma unroll
            for (int i = 0; i < TM; i++) {
                unsigned long long aa = pack2(ra[i], ra[i]);
                #pragma unroll
                for (int j = 0; j < TN/2; j++)
                    fma2(acc2[i][j], aa, rbp[j]);
            }
        }
        if (t + 1 < nt) {
            store_s((t+1) & 1);
            __syncthreads();
        }
    }

    #pragma unroll
    for (int i = 0; i < TM; i++) {
        int gm = brow + trow + i;
        if (gm >= M) continue;
        #pragma unroll
        for (int j = 0; j < TN; j += 4) {
            int gn = bcol + tcol + j;
            float2 p0 = unpack2(acc2[i][j/2]);
            float2 p1 = unpack2(acc2[i][j/2 + 1]);
            float4 v;
            v.x = p0.x + (bias ? bias[gn+0] : 0.f);
            v.y = p0.y + (bias ? bias[gn+1] : 0.f);
            v.z = p1.x + (bias ? bias[gn+2] : 0.f);
            v.w = p1.y + (bias ? bias[gn+3] : 0.f);
            *(float4*)(C + (size_t)gm*N + gn) = v;
        }
    }
}

// ---------------- dual small GEMM (N=32) ----------------
__device__ __forceinline__ void gemm_body32(const float* __restrict__ A, const float* __restrict__ W,
                                            float* __restrict__ C, int K, int browblk) {
    __shared__ float As[2][16][132];
    __shared__ float Ws[2][16][32];
    const int tid  = threadIdx.x;
    const int brow = browblk * 128;
    const int trow = (tid / 8) * 4;
    const int tcol = (tid % 8) * 4;

    float4 stA[2];
    float4 stW;

    auto loadg = [&](int k0) {
        #pragma unroll
        for (int it = 0; it < 2; it++) {
            int i = tid + it*256;
            int m = i / 4, k4 = i % 4;
            int gm = brow + m;
            stA[it] = (gm < NN) ? *(const float4*)(A + (size_t)gm*K + k0 + k4*4)
                                : make_float4(0.f,0.f,0.f,0.f);
        }
        if (tid < 128) {
            int kk = tid / 8, n4 = tid % 8;
            stW = *(const float4*)(W + (size_t)(k0+kk)*32 + n4*4);
        }
    };
    auto store_s = [&](int buf) {
        #pragma unroll
        for (int it = 0; it < 2; it++) {
            int i = tid + it*256;
            int m = i / 4, k4 = i % 4;
            As[buf][k4*4+0][m] = stA[it].x;
            As[buf][k4*4+1][m] = stA[it].y;
            As[buf][k4*4+2][m] = stA[it].z;
            As[buf][k4*4+3][m] = stA[it].w;
        }
        if (tid < 128) {
            int kk = tid / 8, n4 = tid % 8;
            *(float4*)&Ws[buf][kk][n4*4] = stW;
        }
    };

    unsigned long long acc2[4][2];
    #pragma unroll
    for (int i = 0; i < 4; i++) { acc2[i][0] = 0ULL; acc2[i][1] = 0ULL; }

    const int nt = K / 16;
    loadg(0);
    store_s(0);
    __syncthreads();

    for (int t = 0; t < nt; t++) {
        int cur = t & 1;
        if (t + 1 < nt) loadg((t+1)*16);
        #pragma unroll
        for (int kk = 0; kk < 16; kk++) {
            float ra[4], rb[4];
            *(float4*)&ra[0] = *(const float4*)&As[cur][kk][trow];
            *(float4*)&rb[0] = *(const float4*)&Ws[cur][kk][tcol];
            unsigned long long rbp0 = pack2(rb[0], rb[1]);
            unsigned long long rbp1 = pack2(rb[2], rb[3]);
            #pragma unroll
            for (int i = 0; i < 4; i++) {
                unsigned long long aa = pack2(ra[i], ra[i]);
                fma2(acc2[i][0], aa, rbp0);
                fma2(acc2[i][1], aa, rbp1);
            }
        }
        if (t + 1 < nt) {
            store_s((t+1) & 1);
            __syncthreads();
        }
    }

    #pragma unroll
    for (int i = 0; i < 4; i++) {
        int gm = brow + trow + i;
        if (gm >= NN) continue;
        float2 p0 = unpack2(acc2[i][0]);
        float2 p1 = unpack2(acc2[i][1]);
        float4 v = make_float4(p0.x, p0.y, p1.x, p1.y);
        *(float4*)(C + (size_t)gm*32 + tcol) = v;
    }
}

#define NB32 ((NN + 127) / 128)
__global__ void __launch_bounds__(256, 2) gemm_dual() {
    bool second = blockIdx.y >= NB32;
    const float* A = second ? g_axh : g_ay;
    const float* W = second ? g_wh  : g_wbig;
    float*       C = second ? g_o1  : g_xgat;
    int          K = second ? 256   : AYW;
    int        blk = second ? (blockIdx.y - NB32) : blockIdx.y;
    gemm_body32(A, W, C, K, blk);
}

// ---------------- u precompute ----------------
#define GN 32
__global__ void compute_u() {
    extern __shared__ float shm[];
    float (*sW)[132] = (float (*)[132])shm;
    float (*sq)[128] = (float (*)[128])(shm + 128*132);
    int tid = threadIdx.x;
    int n0 = blockIdx.x * GN;
    for (int i = tid; i < 128*128; i += 256) {
        int o = i >> 7, f = i & 127;
        sW[o][f] = g_we2t[i];
    }
    for (int i = tid; i < GN*128; i += 256) {
        int nl = i >> 7, c = i & 127;
        int n = n0 + nl;
        sq[nl][c] = (n < NN) ? g_qkv[(size_t)n*QS + c] : 0.f;
    }
    __syncthreads();
    int w = tid >> 5, lane = tid & 31;
    for (int p = w; p < GN*HH; p += 8) {
        int nl = p >> 2, h = p & 3;
        int n = n0 + nl;
        if (n >= NN) continue;
        float a0=0.f, a1=0.f, a2=0.f, a3=0.f;
        #pragma unroll
        for (int c = 0; c < 32; c++) {
            float qv = sq[nl][h*32 + c];
            const float* row = sW[h*32 + c];
            a0 = fmaf(qv, row[lane],      a0);
            a1 = fmaf(qv, row[lane + 32], a1);
            a2 = fmaf(qv, row[lane + 64], a2);
            a3 = fmaf(qv, row[lane + 96], a3);
        }
        size_t base = (size_t)n*512 + h*128;
        g_u[base + lane]      = a0;
        g_u[base + lane + 32] = a1;
        g_u[base + lane + 64] = a2;
        g_u[base + lane + 96] = a3;
    }
}

// ---------------- fused edge kernel ----------------
__global__ void __launch_bounds__(256, 2)
edge_fused(const int* __restrict__ ei, const float* __restrict__ ea,
           const float* __restrict__ be2, const float* __restrict__ x) {
    const unsigned FULL = 0xffffffffu;
    const int lane = threadIdx.x & 31;
    const int node = (blockIdx.x >> 1) * 8 + (threadIdx.x >> 5);
    if (node >= NN) return;

    if ((blockIdx.x & 1) == 0) {
        // ---- attention: warp per dst node, 2-edge unrolled ----
        const int g = lane >> 3, sub = lane & 7;
        const int d = node;
        const int beg = g_offA[d], end = g_offA[d+1];
        const float scale = 0.17677669529663687f;

        float4 qv = *(const float4*)&g_qkv[(size_t)d*QS + g*32 + sub*4];
        float4 b2 = *(const float4*)&be2[g*32 + sub*4];
        float qb2 = qv.x*b2.x + qv.y*b2.y + qv.z*b2.z + qv.w*b2.w;
        float4 u4[4];
        #pragma unroll
        for (int j = 0; j < 4; j++)
            u4[j] = *(const float4*)&g_u[(size_t)d*512 + g*128 + sub*16 + j*4];

        float4 va = make_float4(0.f,0.f,0.f,0.f);
        float4 y0 = va, y1 = va, y2 = va, y3 = va;
        float s1 = 0.f, s20 = 0.f, s21 = 0.f, s22 = 0.f, s23 = 0.f;

        for (int base = beg; base < end; base += 32) {
            int m = end - base; if (m > 32) m = 32;
            int eL = 0, sL = 0;
            if (base + lane < end) {
                eL = g_payA[base + lane];
                sL = ei[eL];
            }
            int it = 0;
            for (; it + 1 < m; it += 2) {
                int e0 = __shfl_sync(FULL, eL, it),   s0 = __shfl_sync(FULL, sL, it);
                int e1 = __shfl_sync(FULL, eL, it+1), s1i = __shfl_sync(FULL, sL, it+1);
                const float* eb0 = ea + (size_t)e0*128;
                const float* eb1 = ea + (size_t)e1*128;
                const float* r0  = g_qkv + (size_t)s0*QS;
                const float* r1  = g_qkv + (size_t)s1i*QS;

                float4 ka0 = *(const float4*)&r0[128 + g*32 + sub*4];
                float4 ka1 = *(const float4*)&r1[128 + g*32 + sub*4];
                float p1a = qv.x*ka0.x + qv.y*ka0.y + qv.z*ka0.z + qv.w*ka0.w;
                float p1b = qv.x*ka1.x + qv.y*ka1.y + qv.z*ka1.z + qv.w*ka1.w;
                float p2a = qb2, p2b = qb2;
                #pragma unroll
                for (int j = 0; j < 4; j++) {
                    float4 ev0 = *(const float4*)&eb0[sub*16 + j*4];
                    float4 ev1 = *(const float4*)&eb1[sub*16 + j*4];
                    p2a += ev0.x*u4[j].x + ev0.y*u4[j].y + ev0.z*u4[j].z + ev0.w*u4[j].w;
                    p2b += ev1.x*u4[j].x + ev1.y*u4[j].y + ev1.z*u4[j].z + ev1.w*u4[j].w;
                }
                #pragma unroll
                for (int o = 1; o < 8; o <<= 1) {
                    p1a += __shfl_xor_sync(FULL, p1a, o);
                    p2a += __shfl_xor_sync(FULL, p2a, o);
                    p1b += __shfl_xor_sync(FULL, p1b, o);
                    p2b += __shfl_xor_sync(FULL, p2b, o);
                }
                float ex1a = __expf(p1a * scale), ex2a = __expf(p2a * scale);
                float ex1b = __expf(p1b * scale), ex2b = __expf(p2b * scale);
                s1 += ex1a + ex1b;
                float e20a = __shfl_sync(FULL, ex2a, 0),  e20b = __shfl_sync(FULL, ex2b, 0);
                float e21a = __shfl_sync(FULL, ex2a, 8),  e21b = __shfl_sync(FULL, ex2b, 8);
                float e22a = __shfl_sync(FULL, ex2a, 16), e22b = __shfl_sync(FULL, ex2b, 16);
                float e23a = __shfl_sync(FULL, ex2a, 24), e23b = __shfl_sync(FULL, ex2b, 24);
                s20 += e20a + e20b; s21 += e21a + e21b;
                s22 += e22a + e22b; s23 += e23a + e23b;

                float4 ey0 = *(const float4*)&eb0[lane*4];
                float4 ey1 = *(const float4*)&eb1[lane*4];
                float4 vv0 = *(const float4*)&r0[256 + lane*4];
                float4 vv1 = *(const float4*)&r1[256 + lane*4];
                va.x = fmaf(ex1a, vv0.x, fmaf(ex1b, vv1.x, va.x));
                va.y = fmaf(ex1a, vv0.y, fmaf(ex1b, vv1.y, va.y));
                va.z = fmaf(ex1a, vv0.z, fmaf(ex1b, vv1.z, va.z));
                va.w = fmaf(ex1a, vv0.w, fmaf(ex1b, vv1.w, va.w));
                y0.x = fmaf(e20a, ey0.x, fmaf(e20b, ey1.x, y0.x));
                y0.y = fmaf(e20a, ey0.y, fmaf(e20b, ey1.y, y0.y));
                y0.z = fmaf(e20a, ey0.z, fmaf(e20b, ey1.z, y0.z));
                y0.w = fmaf(e20a, ey0.w, fmaf(e20b, ey1.w, y0.w));
                y1.x = fmaf(e21a, ey0.x, fmaf(e21b, ey1.x, y1.x));
                y1.y = fmaf(e21a, ey0.y, fmaf(e21b, ey1.y, y1.y));
                y1.z = fmaf(e21a, ey0.z, fmaf(e21b, ey1.z, y1.z));
                y1.w = fmaf(e21a, ey0.w, fmaf(e21b, ey1.w, y1.w));
                y2.x = fmaf(e22a, ey0.x, fmaf(e22b, ey1.x, y2.x));
                y2.y = fmaf(e22a, ey0.y, fmaf(e22b, ey1.y, y2.y));
                y2.z = fmaf(e22a, ey0.z, fmaf(e22b, ey1.z, y2.z));
                y2.w = fmaf(e22a, ey0.w, fmaf(e22b, ey1.w, y2.w));
                y3.x = fmaf(e23a, ey0.x, fmaf(e23b, ey1.x, y3.x));
                y3.y = fmaf(e23a, ey0.y, fmaf(e23b, ey1.y, y3.y));
                y3.z = fmaf(e23a, ey0.z, fmaf(e23b, ey1.z, y3.z));
                y3.w = fmaf(e23a, ey0.w, fmaf(e23b, ey1.w, y3.w));
            }
            if (it < m) {
                int e0 = __shfl_sync(FULL, eL, it), s0 = __shfl_sync(FULL, sL, it);
                const float* eb0 = ea + (size_t)e0*128;
                const float* r0  = g_qkv + (size_t)s0*QS;
                float4 ka0 = *(const float4*)&r0[128 + g*32 + sub*4];
                float p1a = qv.x*ka0.x + qv.y*ka0.y + qv.z*ka0.z + qv.w*ka0.w;
                float p2a = qb2;
                #pragma unroll
                for (int j = 0; j < 4; j++) {
                    float4 ev0 = *(const float4*)&eb0[sub*16 + j*4];
                    p2a += ev0.x*u4[j].x + ev0.y*u4[j].y + ev0.z*u4[j].z + ev0.w*u4[j].w;
                }
                #pragma unroll
                for (int o = 1; o < 8; o <<= 1) {
                    p1a += __shfl_xor_sync(FULL, p1a, o);
                    p2a += __shfl_xor_sync(FULL, p2a, o);
                }
                float ex1a = __expf(p1a * scale), ex2a = __expf(p2a * scale);
                s1 += ex1a;
                float e20a = __shfl_sync(FULL, ex2a, 0);
                float e21a = __shfl_sync(FULL, ex2a, 8);
                float e22a = __shfl_sync(FULL, ex2a, 16);
                float e23a = __shfl_sync(FULL, ex2a, 24);
                s20 += e20a; s21 += e21a; s22 += e22a; s23 += e23a;
                float4 ey0 = *(const float4*)&eb0[lane*4];
                float4 vv0 = *(const float4*)&r0[256 + lane*4];
                va.x = fmaf(ex1a, vv0.x, va.x); va.y = fmaf(ex1a, vv0.y, va.y);
                va.z = fmaf(ex1a, vv0.z, va.z); va.w = fmaf(ex1a, vv0.w, va.w);
                y0.x = fmaf(e20a, ey0.x, y0.x); y0.y = fmaf(e20a, ey0.y, y0.y);
                y0.z = fmaf(e20a, ey0.z, y0.z); y0.w = fmaf(e20a, ey0.w, y0.w);
                y1.x = fmaf(e21a, ey0.x, y1.x); y1.y = fmaf(e21a, ey0.y, y1.y);
                y1.z = fmaf(e21a, ey0.z, y1.z); y1.w = fmaf(e21a, ey0.w, y1.w);
                y2.x = fmaf(e22a, ey0.x, y2.x); y2.y = fmaf(e22a, ey0.y, y2.y);
                y2.z = fmaf(e22a, ey0.z, y2.z); y2.w = fmaf(e22a, ey0.w, y2.w);
                y3.x = fmaf(e23a, ey0.x, y3.x); y3.y = fmaf(e23a, ey0.y, y3.y);
                y3.z = fmaf(e23a, ey0.z, y3.z); y3.w = fmaf(e23a, ey0.w, y3.w);
            }
        }

        float r1 = 1.f / (s1 + 1e-16f);
        va.x *= r1; va.y *= r1; va.z *= r1; va.w *= r1;
        float q0 = 1.f/(s20+1e-16f), q1 = 1.f/(s21+1e-16f);
        float q2 = 1.f/(s22+1e-16f), q3 = 1.f/(s23+1e-16f);
        y0.x*=q0; y0.y*=q0; y0.z*=q0; y0.w*=q0;
        y1.x*=q1; y1.y*=q1; y1.z*=q1; y1.w*=q1;
        y2.x*=q2; y2.y*=q2; y2.z*=q2; y2.w*=q2;
        y3.x*=q3; y3.y*=q3; y3.z*=q3; y3.w*=q3;

        float* row = g_ay + (size_t)d*AYW;
        *(float4*)&row[lane*4]               = va;
        *(float4*)&row[128 + 0*128 + lane*4] = y0;
        *(float4*)&row[128 + 1*128 + lane*4] = y1;
        *(float4*)&row[128 + 2*128 + lane*4] = y2;
        *(float4*)&row[128 + 3*128 + lane*4] = y3;
        if (lane == 0)      row[640] = (end > beg) ? 1.f : 0.f;
        else if (lane < 16) row[640 + lane] = 0.f;
    } else {
        // ---- hyper aggregation: warp per node, 2-edge unrolled ----
        const int n = node;
        const int beg = g_offH[n], end = g_offH[n+1];
        float4 acc = make_float4(0.f,0.f,0.f,0.f);
        for (int base = beg; base < end; base += 32) {
            int m = end - base; if (m > 32) m = 32;
            int iL = 0;
            if (base + lane < end) iL = g_payH[base + lane];
            int it = 0;
            for (; it + 1 < m; it += 2) {
                int i0 = __shfl_sync(FULL, iL, it);
                int i1 = __shfl_sync(FULL, iL, it+1);
                float4 e0 = *(const float4*)&ea[(size_t)i0*128 + lane*4];
                float4 e1 = *(const float4*)&ea[(size_t)i1*128 + lane*4];
                acc.x += e0.x + e1.x; acc.y += e0.y + e1.y;
                acc.z += e0.z + e1.z; acc.w += e0.w + e1.w;
            }
            if (it < m) {
                int i0 = __shfl_sync(FULL, iL, it);
                float4 e0 = *(const float4*)&ea[(size_t)i0*128 + lane*4];
                acc.x += e0.x; acc.y += e0.y; acc.z += e0.z; acc.w += e0.w;
            }
        }
        int len = end - beg;
        float binv = (len > 0) ? (1.f / (float)len) : 0.f;
        acc.x *= binv; acc.y *= binv; acc.z *= binv; acc.w *= binv;
        *(float4*)&g_axh[(size_t)n*256 + lane*4] = acc;
        *(float4*)&g_axh[(size_t)n*256 + 128 + lane*4] = *(const float4*)&x[(size_t)n*128 + lane*4];
    }
}

// ---------------- merged bn_stats + hyper_out ----------------
__global__ void bn_hyper(const int* __restrict__ ei, const float* __restrict__ bh,
                         float* __restrict__ out2) {
    if (blockIdx.x < 256) {
        __shared__ float ssum[8][CC], ssq[8][CC];
        int c  = threadIdx.x & 31;
        int ry = threadIdx.x >> 5;
        float s = 0.f, q = 0.f;
        for (int r = blockIdx.x * 8 + ry; r < NN; r += 256 * 8) {
            float v = g_xgat[r*CC + c];
            s += v; q += v * v;
        }
        ssum[ry][c] = s; ssq[ry][c] = q;
        __syncthreads();
        if (ry == 0) {
            #pragma unroll
            for (int i = 1; i < 8; i++) { s += ssum[i][c]; q += ssq[i][c]; }
            atomicAdd(&g_sum[c],   (double)s);
            atomicAdd(&g_sumsq[c], (double)q);
        }
    } else {
        int idx = (blockIdx.x - 256) * 256 + threadIdx.x;
        if (idx >= E2*CC) return;
        int i = idx >> 5, c = idx & 31;
        out2[idx] = 0.5f * (g_o1[ei[i]*CC + c] + g_o1[ei[EE + i]*CC + c]) + bh[c];
    }
}

__global__ void bn_final() {
    int c = threadIdx.x;
    if (c < CC) {
        double mu  = g_sum[c] / (double)NN;
        double var = g_sumsq[c] / (double)NN - mu * mu;
        g_mu[c]   = (float)mu;
        g_rstd[c] = (float)(1.0 / sqrt(var + 1e-5));
    }
}

__global__ void bn_apply(const float* __restrict__ bn_w, const float* __restrict__ bn_b,
                         float* __restrict__ out1) {
    int i = blockIdx.x * blockDim.x + threadIdx.x;
    if (i >= NN*CC) return;
    int c = i & 31;
    float xn = bn_w[c] * (g_xgat[i] - g_mu[c]) * g_rstd[c] + bn_b[c];
    out1[i] = 0.5f * xn * (1.0f + erff(xn * 0.70710678118654752f));
}

// ---------------- launcher ----------------
extern "C" void kernel_launch(void* const* d_in, const int* in_sizes, int n_in,
                              void* d_out, int out_size) {
    const float* x    = (const float*)d_in[0];
    const float* ea   = (const float*)d_in[1];
    const float* Wq   = (const float*)d_in[2];
    const float* bq   = (const float*)d_in[3];
    const float* Wk   = (const float*)d_in[4];
    const float* bk   = (const float*)d_in[5];
    const float* Wv   = (const float*)d_in[6];
    const float* bv   = (const float*)d_in[7];
    const float* We2  = (const float*)d_in[8];
    const float* be2  = (const float*)d_in[9];
    const float* We3  = (const float*)d_in[10];
    const float* be3  = (const float*)d_in[11];
    const float* Wcon = (const float*)d_in[12];
    const float* bn_w = (const float*)d_in[13];
    const float* bn_b = (const float*)d_in[14];
    const float* Wh1  = (const float*)d_in[15];
    const float* Wh2  = (const float*)d_in[16];
    const float* bh   = (const float*)d_in[17];
    const int*   ei   = (const int*)d_in[18];

    float* out  = (float*)d_out;
    float* out1 = out;
    float* out2 = out + (size_t)NN * CC;

    float *pqkv, *pwqkv, *pbqkv;
    int *pcntA, *pcntH, *poffA, *poffH, *pcurA, *pcurH, *pblkA, *pblkH;
    cudaGetSymbolAddress((void**)&pqkv,  g_qkv);
    cudaGetSymbolAddress((void**)&pwqkv, g_wqkv);
    cudaGetSymbolAddress((void**)&pbqkv, g_bqkv);
    cudaGetSymbolAddress((void**)&pcntA, g_cntA);
    cudaGetSymbolAddress((void**)&pcntH, g_cntH);
    cudaGetSymbolAddress((void**)&poffA, g_offA);
    cudaGetSymbolAddress((void**)&poffH, g_offH);
    cudaGetSymbolAddress((void**)&pcurA, g_curA);
    cudaGetSymbolAddress((void**)&pcurH, g_curH);
    cudaGetSymbolAddress((void**)&pblkA, g_blkA);
    cudaGetSymbolAddress((void**)&pblkH, g_blkH);

    const int U_SMEM = (128*132 + GN*128) * 4;
    cudaFuncSetAttribute(compute_u, cudaFuncAttributeMaxDynamicSharedMemorySize, U_SMEM);

    setup_kernel<<<256, 256>>>(We2, Wcon, We3, be3, Wh1, Wh2, Wq, bq, Wk, bk, Wv, bv);

    // CSR build
    csr_count<<<(EE + 255)/256, 256>>>(ei);
    scan1<<<NB_SCAN, 1024>>>(pcntA, poffA, pblkA);
    scan1<<<NB_SCAN, 1024>>>(pcntH, poffH, pblkH);
    scan2<<<1, 32>>>(pblkA);
    scan2<<<1, 32>>>(pblkH);
    scan3<<<(NN + 255)/256, 256>>>(poffA, pcurA, pblkA);
    scan3<<<(NN + 255)/256, 256>>>(poffH, pcurH, pblkH);
    csr_fill<<<(EE + 255)/256, 256>>>(ei);

    // fused qkv projection: [50000,128] @ [128,384]
    gemm_bias<128,128,16,8,8><<<dim3(3, (NN + 127)/128), 256>>>(x, pwqkv, pbqkv, pqkv, NN, QS, DINF);

    // u precompute
    compute_u<<<(NN + GN - 1)/GN, 256, U_SMEM>>>();

    // fused attention + hyper aggregation
    edge_fused<<<2 * ((NN + 7)/8), 256>>>(ei, ea, be2, x);

    // both output projections
    gemm_dual<<<dim3(1, 2*NB32), 256>>>();

    // bn stats + hyper edge output
    bn_hyper<<<256 + (E2*CC + 255)/256, 256>>>(ei, bh, out2);
    bn_final<<<1, 32>>>();
    bn_apply<<<(NN * CC + 255) / 256, 256>>>(bn_w, bn_b, out1);
}